// round 9
// baseline (speedup 1.0000x reference)
#include <cuda_runtime.h>
#include <cuda_fp16.h>
#include <math.h>
#include <stdint.h>

#define NN   166
#define NC   64
#define EMB  128
#define LOWD 64
#define FCIN 192
#define BEPS 1e-5f
#define MAXB 8192
#define MAXE 131072

// ---- k_gcn smem layout (bytes; all MMA images 1024-aligned) ----
#define OFF_AD   0        // A_dense fp16 [176 x 192] swz      67584
#define OFF_H1A  67584    // h1 buf0 fp16 [176 x 64] swz       22528
#define OFF_H1B  90112    // h1 buf1 fp16 [176 x 64] swz       22528
#define OFF_WT   112640   // W2^T fp16 [64 x 64] swz            8192
#define OFF_ZT   120832   // z^T fp16 [64 x 192] swz           24576
#define OFF_E    145408   // packed edges (cap 4352)           17408
#define OFF_XS   162816   // x fp32 (498, padded)               2048
#define OFF_Y0   164864   // y0 fp32 (498, padded)              2048
#define OFF_RP   166912   // rowptr (168)                        768
#define OFF_B1   167680   // b1 fp32 (64)
#define OFF_B2   167936   // b2 fp32 (64)
#define OFF_W1   168192   // W1 fp32 (192)
#define OFF_POOL 168960   // pool fp32 (64)
#define GCN_SMEM 169216

// ---------------- device scratch ----------------
__device__ unsigned g_edgesP[MAXE];
__device__ int   g_rowptr[NN + 1];
__device__ float g_Adense[256 * 192];
__device__ float g_sum1[LOWD], g_sq1[LOWD];
__device__ float g_sum2[EMB],  g_sq2[EMB];
__device__ float g_relu_low[MAXB * EMB];
__device__ float g_gfeat[MAXB * NC];

// ---------------- helpers ----------------
__device__ __forceinline__ uint32_t swz(uint32_t o) { return o ^ ((o >> 3) & 0x70); }

__device__ __forceinline__ uint32_t smem_u32(const void* p) {
    uint32_t a;
    asm("{ .reg .u64 t; cvta.to.shared.u64 t, %1; cvt.u32.u64 %0, t; }" : "=r"(a) : "l"(p));
    return a;
}

__device__ __forceinline__ void mma8(float* d, uint32_t a0, uint32_t a1, uint32_t a2, uint32_t a3,
                                     uint32_t b0, uint32_t b1) {
    asm volatile(
        "mma.sync.aligned.m16n8k16.row.col.f32.f16.f16.f32 "
        "{%0,%1,%2,%3}, {%4,%5,%6,%7}, {%8,%9}, {%0,%1,%2,%3};"
        : "+f"(d[0]), "+f"(d[1]), "+f"(d[2]), "+f"(d[3])
        : "r"(a0), "r"(a1), "r"(a2), "r"(a3), "r"(b0), "r"(b1));
}

__device__ __forceinline__ void ldsm4(uint32_t& a0, uint32_t& a1, uint32_t& a2, uint32_t& a3,
                                      uint32_t addr) {
    asm volatile("ldmatrix.sync.aligned.m8n8.x4.shared.b16 {%0,%1,%2,%3}, [%4];"
                 : "=r"(a0), "=r"(a1), "=r"(a2), "=r"(a3) : "r"(addr));
}

__device__ __forceinline__ void stsm4t(uint32_t addr, uint32_t x0, uint32_t x1,
                                       uint32_t x2, uint32_t x3) {
    asm volatile("stmatrix.sync.aligned.m8n8.x4.trans.shared.b16 [%0], {%1,%2,%3,%4};"
                 :: "r"(addr), "r"(x0), "r"(x1), "r"(x2), "r"(x3) : "memory");
}

__device__ __forceinline__ uint32_t packh2(float a, float b) {
    __half2 h = __floats2half2_rn(a, b);
    return *(uint32_t*)&h;
}

// ---------------- CSR + dense A build; zero stats ----------------
__global__ void k_graph(const void* __restrict__ ei_raw, int E) {
    __shared__ int   degs[NN];
    __shared__ float dinvs[NN];
    __shared__ int   curs[NN];
    __shared__ int   rps[NN + 1];
    __shared__ int   is64;

    const int t = threadIdx.x;
    const int* e32 = (const int*)ei_raw;

    for (int i = t; i < 256 * 192; i += 256) g_Adense[i] = 0.f;
    if (t < LOWD) { g_sum1[t] = 0.f; g_sq1[t] = 0.f; }
    if (t < EMB)  { g_sum2[t] = 0.f; g_sq2[t] = 0.f; }

    if (t == 0) {
        int all0 = 1;
        int lim = 2 * E; if (lim > 512) lim = 512;
        for (int i = 1; i < lim; i += 2) if (e32[i] != 0) { all0 = 0; break; }
        is64 = all0;
    }
    if (t < NN) degs[t] = 1;
    __syncthreads();

    const long long* e64 = (const long long*)ei_raw;
    const int w64 = is64;

    for (int e = t; e < E; e += 256) {
        int d = w64 ? (int)e64[E + e] : e32[E + e];
        atomicAdd(&degs[d], 1);
    }
    __syncthreads();
    if (t == 0) {
        rps[0] = 0;
        for (int j = 0; j < NN; j++) rps[j + 1] = rps[j] + degs[j];
    }
    __syncthreads();
    if (t < NN) {
        dinvs[t] = rsqrtf((float)degs[t]);
        curs[t] = rps[t];
        g_rowptr[t] = rps[t];
    }
    if (t == 0) g_rowptr[NN] = rps[NN];
    __syncthreads();
    for (int e = t; e < E; e += 256) {
        int s = w64 ? (int)e64[e] : e32[e];
        int d = w64 ? (int)e64[E + e] : e32[E + e];
        float nw = dinvs[s] * dinvs[d];
        int pos = atomicAdd(&curs[d], 1);
        g_edgesP[pos] = (__float_as_uint(nw) & 0xFFFFFF00u) | (unsigned)s;
        atomicAdd(&g_Adense[d * 192 + s], nw);
    }
    if (t < NN) {
        float nw = dinvs[t] * dinvs[t];
        int pos = atomicAdd(&curs[t], 1);
        g_edgesP[pos] = (__float_as_uint(nw) & 0xFFFFFF00u) | (unsigned)t;
        atomicAdd(&g_Adense[t * 192 + t], nw);
    }
}

// ---------------- column stats of low_dim_features ----------------
__global__ void k_stats1(const float* __restrict__ low, int B) {
    const int t = threadIdx.x;
    const int c = t & 63, rg = t >> 6;
    float s = 0.f, q = 0.f;
    for (int r = blockIdx.x * 4 + rg; r < B; r += gridDim.x * 4) {
        float v = low[r * LOWD + c];
        s += v; q += v * v;
    }
    __shared__ float ss[256], qq[256];
    ss[t] = s; qq[t] = q;
    __syncthreads();
    if (rg == 0) {
        atomicAdd(&g_sum1[c], ss[c] + ss[64 + c] + ss[128 + c] + ss[192 + c]);
        atomicAdd(&g_sq1[c],  qq[c] + qq[64 + c] + qq[128 + c] + qq[192 + c]);
    }
}

// ---------------- bn1 fold + linear + relu + bn2 stats ----------------
__global__ void __launch_bounds__(128) k_lowmlp(const float* __restrict__ low,
                                                const float* __restrict__ gbn, const float* __restrict__ bbn,
                                                const float* __restrict__ Wlow, const float* __restrict__ bllow,
                                                int B) {
    __shared__ float s1[LOWD], t1[LOWD];
    __shared__ float rows[8 * LOWD];
    const int t = threadIdx.x;

    if (t < LOWD) {
        float inv = 1.f / (float)B;
        float mu  = g_sum1[t] * inv;
        float var = g_sq1[t] * inv - mu * mu;
        float sc  = gbn[t] * rsqrtf(var + BEPS);
        s1[t] = sc;
        t1[t] = bbn[t] - mu * sc;
    }
    __syncthreads();

    float w[LOWD];
    float bias = bllow[t];
    #pragma unroll
    for (int k = 0; k < LOWD; k++) {
        float v = Wlow[k * EMB + t];
        w[k] = s1[k] * v;
        bias += t1[k] * v;
    }

    const int spb = (B + gridDim.x - 1) / gridDim.x;
    float ls = 0.f, lq = 0.f;
    const int r8 = t >> 4, q16 = t & 15;

    for (int it = 0; it < spb; it += 8) {
        int base = blockIdx.x * spb + it;
        int rrow = base + r8;
        if (rrow < B)
            ((float4*)rows)[t] = ((const float4*)low)[rrow * 16 + q16];
        __syncthreads();
        #pragma unroll
        for (int s = 0; s < 8; s++) {
            int r = base + s;
            if (r < B) {
                float acc = bias;
                const float4* rp = (const float4*)(rows + s * LOWD);
                #pragma unroll
                for (int k4 = 0; k4 < 16; k4++) {
                    float4 rv = rp[k4];
                    acc += rv.x * w[k4 * 4 + 0];
                    acc += rv.y * w[k4 * 4 + 1];
                    acc += rv.z * w[k4 * 4 + 2];
                    acc += rv.w * w[k4 * 4 + 3];
                }
                acc = fmaxf(acc, 0.f);
                g_relu_low[(size_t)r * EMB + t] = acc;
                ls += acc; lq += acc * acc;
            }
        }
        __syncthreads();
    }
    atomicAdd(&g_sum2[t], ls);
    atomicAdd(&g_sq2[t], lq);
}

// ---------------- persistent fused GCN: warp-specialized pipeline ----------------
__global__ void __launch_bounds__(512) k_gcn(const float* __restrict__ high,
                                             const float* __restrict__ W1, const float* __restrict__ b1,
                                             const float* __restrict__ W2, const float* __restrict__ b2,
                                             int EC, int B) {
    extern __shared__ char sm[];
    const int t = threadIdx.x;
    const int lane = t & 31, w = t >> 5;
    const int g = lane >> 2, tig = lane & 3;
    const bool isCons = (w < 12);
    const int n16 = (w & 3) * 16, mg = w >> 2;   // consumers: mg 0..2

    char* AD = sm + OFF_AD;
    char* WT = sm + OFF_WT;
    float*    xs   = (float*)(sm + OFF_XS);
    float*    y0s  = (float*)(sm + OFF_Y0);
    float*    W1s  = (float*)(sm + OFF_W1);
    float*    b1s  = (float*)(sm + OFF_B1);
    float*    b2s  = (float*)(sm + OFF_B2);
    float*    pool = (float*)(sm + OFF_POOL);
    int*      srp  = (int*)(sm + OFF_RP);
    unsigned* se   = (unsigned*)(sm + OFF_E);

    const uint32_t sb = smem_u32(sm);

    // per-lane ldmatrix/stmatrix address bases
    const int lr = lane & 15, lc8 = (lane >> 4) * 8;
    const uint32_t aH1 = (uint32_t)(lr * 128 + lc8 * 2);   // + mt*2048 + kk*32, swz
    const uint32_t aAD = (uint32_t)(lr * 384 + lc8 * 2);   // + mt*6144 + kk*32, swz
    const int zrow = n16 + (lane & 7) + ((lane >> 4) << 3);
    const uint32_t aZT = (uint32_t)(zrow * 384 + ((lane & 8) ? 16 : 0));  // + kk*32 (ld) / + mt*32 (st)

    // ---- one-time images ----
    for (int i = t; i < 176 * 96; i += 512) {            // A_dense fp16 [176 x 192]
        int r = i / 96, cp = i % 96;
        float2 v = *(const float2*)(g_Adense + r * 192 + cp * 2);
        *(__half2*)(AD + swz((uint32_t)(r * 384 + cp * 4))) = __floats2half2_rn(v.x, v.y);
    }
    for (int i = t; i < 64 * 32; i += 512) {             // W2^T fp16 [64 x 64]
        int n = i >> 5, cp = i & 31;
        *(__half2*)(WT + swz((uint32_t)(n * 128 + cp * 4))) =
            __floats2half2_rn(W2[(2 * cp) * 64 + n], W2[(2 * cp + 1) * 64 + n]);
    }
    for (int i = t; i < 640; i += 512) {                 // zero pad rows 166..175 in BOTH h1 bufs
        int buf = i / 320, r = i % 320;
        int j = 166 + (r >> 5), cp = r & 31;
        char* H1p = sm + (buf ? OFF_H1B : OFF_H1A);
        *(__half2*)(H1p + swz((uint32_t)(j * 128 + cp * 4))) = __floats2half2_rn(0.f, 0.f);
    }
    for (int i = t; i < EC; i += 512) se[i] = g_edgesP[i];
    if (t < NN + 1) srp[t] = g_rowptr[t];
    if (t < 192) W1s[t] = W1[t];
    if (t < 64) { b1s[t] = b1[t]; b2s[t] = b2[t]; }
    __syncthreads();

    // ---- W2 B-fragments preload (consumers, persistent) ----
    uint32_t wfr[4][2][2];
    if (isCons) {
        #pragma unroll
        for (int kk = 0; kk < 4; kk++)
            #pragma unroll
            for (int s = 0; s < 2; s++) {
                int row = n16 + s * 8 + g;
                wfr[kk][s][0] = *(const uint32_t*)(WT + swz((uint32_t)(row * 128 + (kk * 16 + tig * 2) * 2)));
                wfr[kk][s][1] = *(const uint32_t*)(WT + swz((uint32_t)(row * 128 + (kk * 16 + tig * 2 + 8) * 2)));
            }
    }

    const int nIter = (B - 1 - blockIdx.x) / gridDim.x + 1;  // samples this CTA handles

    for (int i = 0; i <= nIter; i++) {
        // ======== producers: build h1 for sample i into buf[i&1] ========
        if (!isCons && i < nIter) {
            const int pb = blockIdx.x + i * gridDim.x;
            char* H1p = sm + ((i & 1) ? OFF_H1B : OFF_H1A);
            const int pt = t - 384;

            for (int j2 = pt; j2 < 249; j2 += 128)
                ((float2*)xs)[j2] = ((const float2*)(high + (size_t)pb * 498))[j2];
            asm volatile("bar.sync 2, 128;" ::: "memory");

            for (int ii = pt; ii < NN * 3; ii += 128) {
                int j = ii / 3, c = ii - j * 3;
                int e0 = srp[j], e1 = srp[j + 1];
                float a = 0.f;
                for (int e = e0; e < e1; e++) {
                    unsigned u = se[e];
                    a += __uint_as_float(u & 0xFFFFFF00u) * xs[(u & 0xFFu) * 3 + c];
                }
                y0s[ii] = a;
            }
            asm volatile("bar.sync 2, 128;" ::: "memory");

            for (int ii = pt; ii < NN * 32; ii += 128) {
                int j = ii >> 5, cp = ii & 31, c = cp * 2;
                float ya = y0s[3 * j], yb = y0s[3 * j + 1], yc = y0s[3 * j + 2];
                float v0 = b1s[c]     + ya * W1s[c]     + yb * W1s[64 + c]     + yc * W1s[128 + c];
                float v1 = b1s[c + 1] + ya * W1s[c + 1] + yb * W1s[64 + c + 1] + yc * W1s[128 + c + 1];
                *(__half2*)(H1p + swz((uint32_t)(j * 128 + cp * 4))) =
                    __floats2half2_rn(fmaxf(v0, 0.f), fmaxf(v1, 0.f));
            }
        }

        // ======== consumers: GEMMs for sample i-1 from buf[(i-1)&1] ========
        if (isCons && i > 0) {
            const int cb = blockIdx.x + (i - 1) * gridDim.x;
            const uint32_t sbH1 = sb + (((i - 1) & 1) ? OFF_H1B : OFF_H1A);

            if (t < 64) pool[t] = 0.f;

            // GEMM1: z = h1 @ W2 -> stmatrix.trans into z^T
            #pragma unroll
            for (int tt = 0; tt < 4; tt++) {
                int mt = mg + 3 * tt;
                if (mt < 11) {
                    float z0[8] = {0, 0, 0, 0, 0, 0, 0, 0};
                    #pragma unroll
                    for (int kk = 0; kk < 4; kk++) {
                        uint32_t a0, a1, a2, a3;
                        ldsm4(a0, a1, a2, a3,
                              sbH1 + swz((uint32_t)(mt * 2048 + kk * 32) + aH1));
                        mma8(z0,     a0, a1, a2, a3, wfr[kk][0][0], wfr[kk][0][1]);
                        mma8(z0 + 4, a0, a1, a2, a3, wfr[kk][1][0], wfr[kk][1][1]);
                    }
                    stsm4t(sb + OFF_ZT + swz(aZT + (uint32_t)(mt * 32)),
                           packh2(z0[0], z0[1]), packh2(z0[2], z0[3]),
                           packh2(z0[4], z0[5]), packh2(z0[6], z0[7]));
                }
            }
            asm volatile("bar.sync 1, 384;" ::: "memory");

            // GEMM2: h2 = A_dense @ z ; fused bias+relu+pool
            uint32_t bfr[11][4];
            #pragma unroll
            for (int kk = 0; kk < 11; kk++)
                ldsm4(bfr[kk][0], bfr[kk][1], bfr[kk][2], bfr[kk][3],
                      sb + OFF_ZT + swz(aZT + (uint32_t)(kk * 32)));

            float pacc[4] = {0, 0, 0, 0};
            #pragma unroll
            for (int tt = 0; tt < 4; tt++) {
                int mt = mg + 3 * tt;
                if (mt < 11) {
                    float d0[8] = {0, 0, 0, 0, 0, 0, 0, 0};
                    #pragma unroll
                    for (int kk = 0; kk < 11; kk++) {
                        uint32_t a0, a1, a2, a3;
                        ldsm4(a0, a1, a2, a3,
                              sb + OFF_AD + swz((uint32_t)(mt * 6144 + kk * 32) + aAD));
                        mma8(d0,     a0, a1, a2, a3, bfr[kk][0], bfr[kk][1]);
                        mma8(d0 + 4, a0, a1, a2, a3, bfr[kk][2], bfr[kk][3]);
                    }
                    int m0 = mt * 16 + g;
                    bool v0 = (m0 < NN), v1 = (m0 + 8 < NN);
                    #pragma unroll
                    for (int s = 0; s < 2; s++) {
                        int c = n16 + s * 8 + tig * 2;
                        float bb0 = b2s[c], bb1 = b2s[c + 1];
                        if (v0) {
                            pacc[s * 2]     += fmaxf(d0[s * 4 + 0] + bb0, 0.f);
                            pacc[s * 2 + 1] += fmaxf(d0[s * 4 + 1] + bb1, 0.f);
                        }
                        if (v1) {
                            pacc[s * 2]     += fmaxf(d0[s * 4 + 2] + bb0, 0.f);
                            pacc[s * 2 + 1] += fmaxf(d0[s * 4 + 3] + bb1, 0.f);
                        }
                    }
                }
            }
            #pragma unroll
            for (int o = 4; o <= 16; o <<= 1) {
                pacc[0] += __shfl_xor_sync(0xffffffffu, pacc[0], o);
                pacc[1] += __shfl_xor_sync(0xffffffffu, pacc[1], o);
                pacc[2] += __shfl_xor_sync(0xffffffffu, pacc[2], o);
                pacc[3] += __shfl_xor_sync(0xffffffffu, pacc[3], o);
            }
            if (g == 0) {
                atomicAdd(&pool[n16 + tig * 2],         pacc[0]);
                atomicAdd(&pool[n16 + tig * 2 + 1],     pacc[1]);
                atomicAdd(&pool[n16 + 8 + tig * 2],     pacc[2]);
                atomicAdd(&pool[n16 + 8 + tig * 2 + 1], pacc[3]);
            }
            asm volatile("bar.sync 1, 384;" ::: "memory");
            if (t < 64) g_gfeat[(size_t)cb * NC + t] = pool[t] * (1.f / (float)NN);
        }
        __syncthreads();
    }
}

// ---------------- head: bn2 fold (local) + fc1 + relu + classifier + log_softmax ----------------
__global__ void __launch_bounds__(256) k_head(const float* __restrict__ Wfc1, const float* __restrict__ bfc1,
                                              const float* __restrict__ glow, const float* __restrict__ blow,
                                              const float* __restrict__ Wcls, const float* __restrict__ bcls,
                                              float* __restrict__ out, int B) {
    const int t = threadIdx.x;
    const int c = t & 127;
    const int kh = t >> 7;

    __shared__ float s2[EMB], t2[EMB];
    __shared__ float comb[FCIN];
    __shared__ float partial[2 * EMB];
    __shared__ float bfcs[EMB];
    __shared__ float wcl0[EMB], wcl1[EMB];
    __shared__ float red[8];

    if (t < EMB) {
        float inv = 1.f / (float)B;
        float mu  = g_sum2[t] * inv;
        float var = g_sq2[t] * inv - mu * mu;
        float sc  = glow[t] * rsqrtf(var + BEPS);
        s2[t] = sc;
        t2[t] = blow[t] - mu * sc;
    }
    __syncthreads();

    float w[96];
    #pragma unroll
    for (int i = 0; i < 96; i++) {
        int row = kh * 96 + i;
        float v = Wfc1[row * EMB + c];
        if (row >= NC) v *= s2[row - NC];
        w[i] = v;
    }
    if (t < EMB) {
        float acc = bfc1[t];
        for (int k = 0; k < EMB; k++) acc += t2[k] * Wfc1[(NC + k) * EMB + t];
        bfcs[t] = acc;
        wcl0[t] = Wcls[t * 2];
        wcl1[t] = Wcls[t * 2 + 1];
    }

    const int spb = (B + gridDim.x - 1) / gridDim.x;
    __syncthreads();

    for (int it = 0; it < spb; it++) {
        int s = blockIdx.x * spb + it;
        bool valid = (s < B);
        if (valid) {
            if (t < NC) comb[t] = g_gfeat[(size_t)s * NC + t];
            int u = t - NC;
            if (u >= 0 && u < EMB) comb[NC + u] = g_relu_low[(size_t)s * EMB + u];
        }
        __syncthreads();
        if (valid) {
            const float* cb = comb + kh * 96;
            float a0 = 0.f, a1 = 0.f, a2 = 0.f, a3 = 0.f;
            #pragma unroll
            for (int i = 0; i < 96; i += 4) {
                a0 += w[i] * cb[i];
                a1 += w[i + 1] * cb[i + 1];
                a2 += w[i + 2] * cb[i + 2];
                a3 += w[i + 3] * cb[i + 3];
            }
            partial[kh * EMB + c] = (a0 + a1) + (a2 + a3);
        }
        __syncthreads();
        if (valid && kh == 0) {
            float h = fmaxf(partial[c] + partial[EMB + c] + bfcs[c], 0.f);
            float p0 = h * wcl0[c];
            float p1 = h * wcl1[c];
            #pragma unroll
            for (int o = 16; o > 0; o >>= 1) {
                p0 += __shfl_down_sync(0xffffffffu, p0, o);
                p1 += __shfl_down_sync(0xffffffffu, p1, o);
            }
            if ((c & 31) == 0) { red[c >> 5] = p0; red[4 + (c >> 5)] = p1; }
        }
        __syncthreads();
        if (valid && t == 0) {
            float l0 = red[0] + red[1] + red[2] + red[3] + bcls[0];
            float l1 = red[4] + red[5] + red[6] + red[7] + bcls[1];
            float m = fmaxf(l0, l1);
            float lse = m + logf(expf(l0 - m) + expf(l1 - m));
            out[(size_t)s * 2 + 0] = l0 - lse;
            out[(size_t)s * 2 + 1] = l1 - lse;
        }
        __syncthreads();
    }
}

// ---------------- launch ----------------
extern "C" void kernel_launch(void* const* d_in, const int* in_sizes, int n_in,
                              void* d_out, int out_size) {
    const float* high  = (const float*)d_in[0];
    const float* low   = (const float*)d_in[1];
    const void*  ei    = d_in[2];
    const float* g_bn  = (const float*)d_in[3];
    const float* b_bn  = (const float*)d_in[4];
    const float* W_low = (const float*)d_in[5];
    const float* bl_lw = (const float*)d_in[6];
    const float* g_lo  = (const float*)d_in[7];
    const float* b_lo  = (const float*)d_in[8];
    const float* W1    = (const float*)d_in[9];
    const float* b1    = (const float*)d_in[10];
    const float* W2    = (const float*)d_in[11];
    const float* b2    = (const float*)d_in[12];
    const float* Wfc1  = (const float*)d_in[13];
    const float* bfc1  = (const float*)d_in[14];
    const float* Wcls  = (const float*)d_in[15];
    const float* bcls  = (const float*)d_in[16];

    int B = in_sizes[0] / (NN * 3);
    int E = in_sizes[2] / 2;
    int EC = E + NN;
    if (EC > 4352) EC = 4352;
    float* out = (float*)d_out;

    k_graph<<<1, 256>>>(ei, E);
    k_stats1<<<64, 256>>>(low, B);
    k_lowmlp<<<128, 128>>>(low, g_bn, b_bn, W_low, bl_lw, B);

    cudaFuncSetAttribute(k_gcn, cudaFuncAttributeMaxDynamicSharedMemorySize, GCN_SMEM);
    int grid = 148;
    if (grid > B) grid = B;
    k_gcn<<<grid, 512, GCN_SMEM>>>(high, W1, b1, W2, b2, EC, B);

    k_head<<<128, 256>>>(Wfc1, bfc1, g_lo, b_lo, Wcls, bcls, out, B);
}

// round 12
// speedup vs baseline: 1.1324x; 1.1324x over previous
#include <cuda_runtime.h>
#include <cuda_fp16.h>
#include <math.h>
#include <stdint.h>

#define NN   166
#define NC   64
#define EMB  128
#define LOWD 64
#define FCIN 192
#define BEPS 1e-5f
#define MAXB 8192
#define MAXE 131072

// ---- k_gcn smem layout (bytes; every image offset 1024-aligned) ----
#define OFF_AD   0        // A_dense fp16 [176 x 192] swz      67584
#define OFF_H1   67584    // h1 fp16 [176 x 64] swz            22528
#define OFF_WT   90112    // W2^T fp16 [64 x 64] swz            8192
#define OFF_ZT   98304    // z^T fp16 [64 x 192] swz           24576
#define OFF_E    122880   // packed edges (cap 4352)           17408
#define OFF_XS   140288   // x fp32 (498, padded)               2048
#define OFF_Y0   142336   // y0 fp32 (498, padded)              2048
#define OFF_RP   144384   // rowptr (168)                        672
#define OFF_B1   145056   // b1 fp32 (64)
#define OFF_B2   145312   // b2 fp32 (64)
#define OFF_W1   145568   // W1 fp32 (192)
#define OFF_POOL 146336   // pool fp32 (64)
#define GCN_SMEM 146592

// ---------------- device scratch ----------------
__device__ unsigned g_edgesP[MAXE];
__device__ int   g_rowptr[NN + 1];
__device__ float g_Adense[256 * 192];
__device__ float g_sum1[LOWD], g_sq1[LOWD];
__device__ float g_sum2[EMB],  g_sq2[EMB];
__device__ float g_relu_low[MAXB * EMB];
__device__ float g_gfeat[MAXB * NC];

// ---------------- helpers ----------------
__device__ __forceinline__ uint32_t swz(uint32_t o) { return o ^ ((o >> 3) & 0x70); }

__device__ __forceinline__ uint32_t smem_u32(const void* p) {
    uint32_t a;
    asm("{ .reg .u64 t; cvta.to.shared.u64 t, %1; cvt.u32.u64 %0, t; }" : "=r"(a) : "l"(p));
    return a;
}

__device__ __forceinline__ void mma8(float* d, uint32_t a0, uint32_t a1, uint32_t a2, uint32_t a3,
                                     uint32_t b0, uint32_t b1) {
    asm volatile(
        "mma.sync.aligned.m16n8k16.row.col.f32.f16.f16.f32 "
        "{%0,%1,%2,%3}, {%4,%5,%6,%7}, {%8,%9}, {%0,%1,%2,%3};"
        : "+f"(d[0]), "+f"(d[1]), "+f"(d[2]), "+f"(d[3])
        : "r"(a0), "r"(a1), "r"(a2), "r"(a3), "r"(b0), "r"(b1));
}

__device__ __forceinline__ void ldsm4(uint32_t& a0, uint32_t& a1, uint32_t& a2, uint32_t& a3,
                                      uint32_t addr) {
    asm volatile("ldmatrix.sync.aligned.m8n8.x4.shared.b16 {%0,%1,%2,%3}, [%4];"
                 : "=r"(a0), "=r"(a1), "=r"(a2), "=r"(a3) : "r"(addr));
}

__device__ __forceinline__ void stsm4t(uint32_t addr, uint32_t x0, uint32_t x1,
                                       uint32_t x2, uint32_t x3) {
    asm volatile("stmatrix.sync.aligned.m8n8.x4.trans.shared.b16 [%0], {%1,%2,%3,%4};"
                 :: "r"(addr), "r"(x0), "r"(x1), "r"(x2), "r"(x3) : "memory");
}

__device__ __forceinline__ uint32_t packh2(float a, float b) {
    __half2 h = __floats2half2_rn(a, b);
    return *(uint32_t*)&h;
}

// ---------------- CSR + dense A build; zero stats ----------------
__global__ void k_graph(const void* __restrict__ ei_raw, int E) {
    __shared__ int   degs[NN];
    __shared__ float dinvs[NN];
    __shared__ int   curs[NN];
    __shared__ int   rps[NN + 1];
    __shared__ int   is64;

    const int t = threadIdx.x;
    const int* e32 = (const int*)ei_raw;

    for (int i = t; i < 256 * 192; i += 256) g_Adense[i] = 0.f;
    if (t < LOWD) { g_sum1[t] = 0.f; g_sq1[t] = 0.f; }
    if (t < EMB)  { g_sum2[t] = 0.f; g_sq2[t] = 0.f; }

    if (t == 0) {
        int all0 = 1;
        int lim = 2 * E; if (lim > 512) lim = 512;
        for (int i = 1; i < lim; i += 2) if (e32[i] != 0) { all0 = 0; break; }
        is64 = all0;
    }
    if (t < NN) degs[t] = 1;
    __syncthreads();

    const long long* e64 = (const long long*)ei_raw;
    const int w64 = is64;

    for (int e = t; e < E; e += 256) {
        int d = w64 ? (int)e64[E + e] : e32[E + e];
        atomicAdd(&degs[d], 1);
    }
    __syncthreads();
    if (t == 0) {
        rps[0] = 0;
        for (int j = 0; j < NN; j++) rps[j + 1] = rps[j] + degs[j];
    }
    __syncthreads();
    if (t < NN) {
        dinvs[t] = rsqrtf((float)degs[t]);
        curs[t] = rps[t];
        g_rowptr[t] = rps[t];
    }
    if (t == 0) g_rowptr[NN] = rps[NN];
    __syncthreads();
    for (int e = t; e < E; e += 256) {
        int s = w64 ? (int)e64[e] : e32[e];
        int d = w64 ? (int)e64[E + e] : e32[E + e];
        float nw = dinvs[s] * dinvs[d];
        int pos = atomicAdd(&curs[d], 1);
        g_edgesP[pos] = (__float_as_uint(nw) & 0xFFFFFF00u) | (unsigned)s;
        atomicAdd(&g_Adense[d * 192 + s], nw);
    }
    if (t < NN) {
        float nw = dinvs[t] * dinvs[t];
        int pos = atomicAdd(&curs[t], 1);
        g_edgesP[pos] = (__float_as_uint(nw) & 0xFFFFFF00u) | (unsigned)t;
        atomicAdd(&g_Adense[t * 192 + t], nw);
    }
}

// ---------------- column stats of low_dim_features ----------------
__global__ void k_stats1(const float* __restrict__ low, int B) {
    const int t = threadIdx.x;
    const int c = t & 63, rg = t >> 6;
    float s = 0.f, q = 0.f;
    for (int r = blockIdx.x * 4 + rg; r < B; r += gridDim.x * 4) {
        float v = low[r * LOWD + c];
        s += v; q += v * v;
    }
    __shared__ float ss[256], qq[256];
    ss[t] = s; qq[t] = q;
    __syncthreads();
    if (rg == 0) {
        atomicAdd(&g_sum1[c], ss[c] + ss[64 + c] + ss[128 + c] + ss[192 + c]);
        atomicAdd(&g_sq1[c],  qq[c] + qq[64 + c] + qq[128 + c] + qq[192 + c]);
    }
}

// ---------------- bn1 fold + linear + relu + bn2 stats ----------------
__global__ void __launch_bounds__(128) k_lowmlp(const float* __restrict__ low,
                                                const float* __restrict__ gbn, const float* __restrict__ bbn,
                                                const float* __restrict__ Wlow, const float* __restrict__ bllow,
                                                int B) {
    __shared__ float s1[LOWD], t1[LOWD];
    __shared__ float rows[8 * LOWD];
    const int t = threadIdx.x;

    if (t < LOWD) {
        float inv = 1.f / (float)B;
        float mu  = g_sum1[t] * inv;
        float var = g_sq1[t] * inv - mu * mu;
        float sc  = gbn[t] * rsqrtf(var + BEPS);
        s1[t] = sc;
        t1[t] = bbn[t] - mu * sc;
    }
    __syncthreads();

    float w[LOWD];
    float bias = bllow[t];
    #pragma unroll
    for (int k = 0; k < LOWD; k++) {
        float v = Wlow[k * EMB + t];
        w[k] = s1[k] * v;
        bias += t1[k] * v;
    }

    const int spb = (B + gridDim.x - 1) / gridDim.x;
    float ls = 0.f, lq = 0.f;
    const int r8 = t >> 4, q16 = t & 15;

    for (int it = 0; it < spb; it += 8) {
        int base = blockIdx.x * spb + it;
        int rrow = base + r8;
        if (rrow < B)
            ((float4*)rows)[t] = ((const float4*)low)[rrow * 16 + q16];
        __syncthreads();
        #pragma unroll
        for (int s = 0; s < 8; s++) {
            int r = base + s;
            if (r < B) {
                float acc = bias;
                const float4* rp = (const float4*)(rows + s * LOWD);
                #pragma unroll
                for (int k4 = 0; k4 < 16; k4++) {
                    float4 rv = rp[k4];
                    acc += rv.x * w[k4 * 4 + 0];
                    acc += rv.y * w[k4 * 4 + 1];
                    acc += rv.z * w[k4 * 4 + 2];
                    acc += rv.w * w[k4 * 4 + 3];
                }
                acc = fmaxf(acc, 0.f);
                g_relu_low[(size_t)r * EMB + t] = acc;
                ls += acc; lq += acc * acc;
            }
        }
        __syncthreads();
    }
    atomicAdd(&g_sum2[t], ls);
    atomicAdd(&g_sq2[t], lq);
}

// ---------------- persistent fused GCN: mma.sync + ldmatrix/stmatrix, split accumulators ----------------
__global__ void __launch_bounds__(512) k_gcn(const float* __restrict__ high,
                                             const float* __restrict__ W1, const float* __restrict__ b1,
                                             const float* __restrict__ W2, const float* __restrict__ b2,
                                             int EC, int B) {
    extern __shared__ char sm[];
    const int t = threadIdx.x;
    const int lane = t & 31, w = t >> 5;
    const int g = lane >> 2, tig = lane & 3;
    const int n16 = (w & 3) * 16, mg = w >> 2;

    char* AD = sm + OFF_AD;
    char* H1 = sm + OFF_H1;
    char* WT = sm + OFF_WT;
    float*    xs   = (float*)(sm + OFF_XS);
    float*    y0s  = (float*)(sm + OFF_Y0);
    float*    W1s  = (float*)(sm + OFF_W1);
    float*    b1s  = (float*)(sm + OFF_B1);
    float*    b2s  = (float*)(sm + OFF_B2);
    float*    pool = (float*)(sm + OFF_POOL);
    int*      srp  = (int*)(sm + OFF_RP);
    unsigned* se   = (unsigned*)(sm + OFF_E);

    const uint32_t sb = smem_u32(sm);

    // per-lane ldmatrix/stmatrix address bases
    const int lr = lane & 15, lc8 = (lane >> 4) * 8;
    const uint32_t aH1 = (uint32_t)(lr * 128 + lc8 * 2);   // + mt*2048 + kk*32, swz
    const uint32_t aAD = (uint32_t)(lr * 384 + lc8 * 2);   // + mt*6144 + kk*32, swz
    const int zrow = n16 + (lane & 7) + ((lane >> 4) << 3);
    const uint32_t aZT = (uint32_t)(zrow * 384 + ((lane & 8) ? 16 : 0));  // + kk*32 (ld) / + mt*32 (st)

    // ---- one-time images ----
    for (int i = t; i < 176 * 96; i += 512) {            // A_dense fp16 [176 x 192]
        int r = i / 96, cp = i % 96;
        float2 v = *(const float2*)(g_Adense + r * 192 + cp * 2);
        *(__half2*)(AD + swz((uint32_t)(r * 384 + cp * 4))) = __floats2half2_rn(v.x, v.y);
    }
    for (int i = t; i < 64 * 32; i += 512) {             // W2^T fp16 [64 x 64]
        int n = i >> 5, cp = i & 31;
        *(__half2*)(WT + swz((uint32_t)(n * 128 + cp * 4))) =
            __floats2half2_rn(W2[(2 * cp) * 64 + n], W2[(2 * cp + 1) * 64 + n]);
    }
    if (t < 320) {                                       // zero h1 pad rows 166..175
        int j = 166 + (t >> 5), cp = t & 31;
        *(__half2*)(H1 + swz((uint32_t)(j * 128 + cp * 4))) = __floats2half2_rn(0.f, 0.f);
    }
    for (int i = t; i < EC; i += 512) se[i] = g_edgesP[i];
    if (t < NN + 1) srp[t] = g_rowptr[t];
    if (t < 192) W1s[t] = W1[t];
    if (t < 64) { b1s[t] = b1[t]; b2s[t] = b2[t]; }
    __syncthreads();

    // ---- preload W2 B-fragments (persistent across samples) ----
    uint32_t wfr[4][2][2];
    #pragma unroll
    for (int kk = 0; kk < 4; kk++)
        #pragma unroll
        for (int s = 0; s < 2; s++) {
            int row = n16 + s * 8 + g;
            wfr[kk][s][0] = *(const uint32_t*)(WT + swz((uint32_t)(row * 128 + (kk * 16 + tig * 2) * 2)));
            wfr[kk][s][1] = *(const uint32_t*)(WT + swz((uint32_t)(row * 128 + (kk * 16 + tig * 2 + 8) * 2)));
        }

    for (int b = blockIdx.x; b < B; b += gridDim.x) {
        // 1. zero pool; load x
        if (t < 64) pool[t] = 0.f;
        if (t < 249) ((float2*)xs)[t] = ((const float2*)(high + (size_t)b * 498))[t];
        __syncthreads();

        // 2. y0 = A x (sparse, 3 channels)
        if (t < NN * 3) {
            int j = t / 3, c = t - j * 3;
            int e0 = srp[j], e1 = srp[j + 1];
            float a = 0.f;
            for (int e = e0; e < e1; e++) {
                unsigned u = se[e];
                a += __uint_as_float(u & 0xFFFFFF00u) * xs[(u & 0xFFu) * 3 + c];
            }
            y0s[t] = a;
        }
        __syncthreads();

        // 3. h1 = relu(y0 W1 + b1) -> fp16 image
        for (int i = t; i < NN * 32; i += 512) {
            int j = i >> 5, cp = i & 31, c = cp * 2;
            float ya = y0s[3 * j], yb = y0s[3 * j + 1], yc = y0s[3 * j + 2];
            float v0 = b1s[c]     + ya * W1s[c]     + yb * W1s[64 + c]     + yc * W1s[128 + c];
            float v1 = b1s[c + 1] + ya * W1s[c + 1] + yb * W1s[64 + c + 1] + yc * W1s[128 + c + 1];
            *(__half2*)(H1 + swz((uint32_t)(j * 128 + cp * 4))) =
                __floats2half2_rn(fmaxf(v0, 0.f), fmaxf(v1, 0.f));
        }
        __syncthreads();

        // 4. GEMM1: z = h1 @ W2 -> stmatrix.trans into z^T
        #pragma unroll
        for (int tt = 0; tt < 3; tt++) {
            int mt = mg + 4 * tt;
            if (mt < 11) {
                float z0[8] = {0, 0, 0, 0, 0, 0, 0, 0};
                #pragma unroll
                for (int kk = 0; kk < 4; kk++) {
                    uint32_t a0, a1, a2, a3;
                    ldsm4(a0, a1, a2, a3,
                          sb + OFF_H1 + swz((uint32_t)(mt * 2048 + kk * 32) + aH1));
                    mma8(z0,     a0, a1, a2, a3, wfr[kk][0][0], wfr[kk][0][1]);
                    mma8(z0 + 4, a0, a1, a2, a3, wfr[kk][1][0], wfr[kk][1][1]);
                }
                stsm4t(sb + OFF_ZT + swz(aZT + (uint32_t)(mt * 32)),
                       packh2(z0[0], z0[1]), packh2(z0[2], z0[3]),
                       packh2(z0[4], z0[5]), packh2(z0[6], z0[7]));
            }
        }
        __syncthreads();

        // 5. GEMM2: h2 = A_dense @ z ; split accumulators (kk parity) for chain ILP
        uint32_t bfr[11][4];
        #pragma unroll
        for (int kk = 0; kk < 11; kk++)
            ldsm4(bfr[kk][0], bfr[kk][1], bfr[kk][2], bfr[kk][3],
                  sb + OFF_ZT + swz(aZT + (uint32_t)(kk * 32)));

        float pacc[4] = {0, 0, 0, 0};
        #pragma unroll
        for (int tt = 0; tt < 3; tt++) {
            int mt = mg + 4 * tt;
            if (mt < 11) {
                float dA[8] = {0, 0, 0, 0, 0, 0, 0, 0};
                float dB[8] = {0, 0, 0, 0, 0, 0, 0, 0};
                #pragma unroll
                for (int kk = 0; kk < 11; kk++) {
                    uint32_t a0, a1, a2, a3;
                    ldsm4(a0, a1, a2, a3,
                          sb + OFF_AD + swz((uint32_t)(mt * 6144 + kk * 32) + aAD));
                    float* dst = (kk & 1) ? dB : dA;
                    mma8(dst,     a0, a1, a2, a3, bfr[kk][0], bfr[kk][1]);
                    mma8(dst + 4, a0, a1, a2, a3, bfr[kk][2], bfr[kk][3]);
                }
                int m0 = mt * 16 + g;
                bool v0 = (m0 < NN), v1 = (m0 + 8 < NN);
                #pragma unroll
                for (int s = 0; s < 2; s++) {
                    int c = n16 + s * 8 + tig * 2;
                    float bb0 = b2s[c], bb1 = b2s[c + 1];
                    float e0 = dA[s * 4 + 0] + dB[s * 4 + 0];
                    float e1 = dA[s * 4 + 1] + dB[s * 4 + 1];
                    float e2 = dA[s * 4 + 2] + dB[s * 4 + 2];
                    float e3 = dA[s * 4 + 3] + dB[s * 4 + 3];
                    if (v0) {
                        pacc[s * 2]     += fmaxf(e0 + bb0, 0.f);
                        pacc[s * 2 + 1] += fmaxf(e1 + bb1, 0.f);
                    }
                    if (v1) {
                        pacc[s * 2]     += fmaxf(e2 + bb0, 0.f);
                        pacc[s * 2 + 1] += fmaxf(e3 + bb1, 0.f);
                    }
                }
            }
        }
        // reduce over g (lane bits 2..4), then one atomic per surviving lane
        #pragma unroll
        for (int o = 4; o <= 16; o <<= 1) {
            pacc[0] += __shfl_xor_sync(0xffffffffu, pacc[0], o);
            pacc[1] += __shfl_xor_sync(0xffffffffu, pacc[1], o);
            pacc[2] += __shfl_xor_sync(0xffffffffu, pacc[2], o);
            pacc[3] += __shfl_xor_sync(0xffffffffu, pacc[3], o);
        }
        if (g == 0) {
            atomicAdd(&pool[n16 + tig * 2],         pacc[0]);
            atomicAdd(&pool[n16 + tig * 2 + 1],     pacc[1]);
            atomicAdd(&pool[n16 + 8 + tig * 2],     pacc[2]);
            atomicAdd(&pool[n16 + 8 + tig * 2 + 1], pacc[3]);
        }
        __syncthreads();
        if (t < 64) g_gfeat[(size_t)b * NC + t] = pool[t] * (1.f / (float)NN);
        __syncthreads();
    }
}

// ---------------- head: bn2 fold (local) + fc1 + relu + classifier + log_softmax ----------------
__global__ void __launch_bounds__(256) k_head(const float* __restrict__ Wfc1, const float* __restrict__ bfc1,
                                              const float* __restrict__ glow, const float* __restrict__ blow,
                                              const float* __restrict__ Wcls, const float* __restrict__ bcls,
                                              float* __restrict__ out, int B) {
    const int t = threadIdx.x;
    const int c = t & 127;
    const int kh = t >> 7;

    __shared__ float s2[EMB], t2[EMB];
    __shared__ float comb[FCIN];
    __shared__ float partial[2 * EMB];
    __shared__ float bfcs[EMB];
    __shared__ float wcl0[EMB], wcl1[EMB];
    __shared__ float red[8];

    if (t < EMB) {
        float inv = 1.f / (float)B;
        float mu  = g_sum2[t] * inv;
        float var = g_sq2[t] * inv - mu * mu;
        float sc  = glow[t] * rsqrtf(var + BEPS);
        s2[t] = sc;
        t2[t] = blow[t] - mu * sc;
    }
    __syncthreads();

    float w[96];
    #pragma unroll
    for (int i = 0; i < 96; i++) {
        int row = kh * 96 + i;
        float v = Wfc1[row * EMB + c];
        if (row >= NC) v *= s2[row - NC];
        w[i] = v;
    }
    if (t < EMB) {
        float acc = bfc1[t];
        for (int k = 0; k < EMB; k++) acc += t2[k] * Wfc1[(NC + k) * EMB + t];
        bfcs[t] = acc;
        wcl0[t] = Wcls[t * 2];
        wcl1[t] = Wcls[t * 2 + 1];
    }

    const int spb = (B + gridDim.x - 1) / gridDim.x;
    __syncthreads();

    for (int it = 0; it < spb; it++) {
        int s = blockIdx.x * spb + it;
        bool valid = (s < B);
        if (valid) {
            if (t < NC) comb[t] = g_gfeat[(size_t)s * NC + t];
            int u = t - NC;
            if (u >= 0 && u < EMB) comb[NC + u] = g_relu_low[(size_t)s * EMB + u];
        }
        __syncthreads();
        if (valid) {
            const float* cb = comb + kh * 96;
            float a0 = 0.f, a1 = 0.f, a2 = 0.f, a3 = 0.f;
            #pragma unroll
            for (int i = 0; i < 96; i += 4) {
                a0 += w[i] * cb[i];
                a1 += w[i + 1] * cb[i + 1];
                a2 += w[i + 2] * cb[i + 2];
                a3 += w[i + 3] * cb[i + 3];
            }
            partial[kh * EMB + c] = (a0 + a1) + (a2 + a3);
        }
        __syncthreads();
        if (valid && kh == 0) {
            float h = fmaxf(partial[c] + partial[EMB + c] + bfcs[c], 0.f);
            float p0 = h * wcl0[c];
            float p1 = h * wcl1[c];
            #pragma unroll
            for (int o = 16; o > 0; o >>= 1) {
                p0 += __shfl_down_sync(0xffffffffu, p0, o);
                p1 += __shfl_down_sync(0xffffffffu, p1, o);
            }
            if ((c & 31) == 0) { red[c >> 5] = p0; red[4 + (c >> 5)] = p1; }
        }
        __syncthreads();
        if (valid && t == 0) {
            float l0 = red[0] + red[1] + red[2] + red[3] + bcls[0];
            float l1 = red[4] + red[5] + red[6] + red[7] + bcls[1];
            float m = fmaxf(l0, l1);
            float lse = m + logf(expf(l0 - m) + expf(l1 - m));
            out[(size_t)s * 2 + 0] = l0 - lse;
            out[(size_t)s * 2 + 1] = l1 - lse;
        }
        __syncthreads();
    }
}

// ---------------- launch ----------------
extern "C" void kernel_launch(void* const* d_in, const int* in_sizes, int n_in,
                              void* d_out, int out_size) {
    const float* high  = (const float*)d_in[0];
    const float* low   = (const float*)d_in[1];
    const void*  ei    = d_in[2];
    const float* g_bn  = (const float*)d_in[3];
    const float* b_bn  = (const float*)d_in[4];
    const float* W_low = (const float*)d_in[5];
    const float* bl_lw = (const float*)d_in[6];
    const float* g_lo  = (const float*)d_in[7];
    const float* b_lo  = (const float*)d_in[8];
    const float* W1    = (const float*)d_in[9];
    const float* b1    = (const float*)d_in[10];
    const float* W2    = (const float*)d_in[11];
    const float* b2    = (const float*)d_in[12];
    const float* Wfc1  = (const float*)d_in[13];
    const float* bfc1  = (const float*)d_in[14];
    const float* Wcls  = (const float*)d_in[15];
    const float* bcls  = (const float*)d_in[16];

    int B = in_sizes[0] / (NN * 3);
    int E = in_sizes[2] / 2;
    int EC = E + NN;
    if (EC > 4352) EC = 4352;
    float* out = (float*)d_out;

    k_graph<<<1, 256>>>(ei, E);
    k_stats1<<<64, 256>>>(low, B);
    k_lowmlp<<<256, 128>>>(low, g_bn, b_bn, W_low, bl_lw, B);

    cudaFuncSetAttribute(k_gcn, cudaFuncAttributeMaxDynamicSharedMemorySize, GCN_SMEM);
    int grid = 148;
    if (grid > B) grid = B;
    k_gcn<<<grid, 512, GCN_SMEM>>>(high, W1, b1, W2, b2, EC, B);

    k_head<<<296, 256>>>(Wfc1, bfc1, g_lo, b_lo, Wcls, bcls, out, B);
}

// round 14
// speedup vs baseline: 1.3418x; 1.1850x over previous
#include <cuda_runtime.h>
#include <cuda_fp16.h>
#include <math.h>
#include <stdint.h>

#define NN   166
#define NC   64
#define EMB  128
#define LOWD 64
#define FCIN 192
#define BEPS 1e-5f
#define MAXB 8192

// ---- k_gcn smem layout (bytes; images 1024-aligned) ----
#define OFF_AD   0        // A_dense fp16 [176 x 192] swz      67584
#define OFF_H1   67584    // h1 fp16 [176 x 64] swz            22528
#define OFF_WT   90112    // W2^T fp16 [64 x 64] swz            8192
#define OFF_ZT   98304    // z^T fp16 [64 x 192] swz           24576
#define OFF_XP   122880   // x^T fp16 [16 x 192] swz            6144
#define OFF_B1   129024   // b1 fp32 (64)
#define OFF_B2   129280   // b2 fp32 (64)
#define OFF_W1   129536   // W1 fp32 (192)
#define OFF_POOL 130304   // pool fp32 (64)
#define GCN_SMEM 130560

// ---------------- device scratch ----------------
__device__ float g_Adense[256 * 192];
__device__ float g_sum1[LOWD], g_sq1[LOWD];
__device__ float g_sum2[EMB],  g_sq2[EMB];
__device__ float g_relu_low[MAXB * EMB];
__device__ float g_gfeat[MAXB * NC];

// ---------------- helpers ----------------
__device__ __forceinline__ uint32_t swz(uint32_t o) { return o ^ ((o >> 3) & 0x70); }

__device__ __forceinline__ uint32_t smem_u32(const void* p) {
    uint32_t a;
    asm("{ .reg .u64 t; cvta.to.shared.u64 t, %1; cvt.u32.u64 %0, t; }" : "=r"(a) : "l"(p));
    return a;
}

__device__ __forceinline__ void mma8(float* d, uint32_t a0, uint32_t a1, uint32_t a2, uint32_t a3,
                                     uint32_t b0, uint32_t b1) {
    asm volatile(
        "mma.sync.aligned.m16n8k16.row.col.f32.f16.f16.f32 "
        "{%0,%1,%2,%3}, {%4,%5,%6,%7}, {%8,%9}, {%0,%1,%2,%3};"
        : "+f"(d[0]), "+f"(d[1]), "+f"(d[2]), "+f"(d[3])
        : "r"(a0), "r"(a1), "r"(a2), "r"(a3), "r"(b0), "r"(b1));
}

__device__ __forceinline__ void ldsm4(uint32_t& a0, uint32_t& a1, uint32_t& a2, uint32_t& a3,
                                      uint32_t addr) {
    asm volatile("ldmatrix.sync.aligned.m8n8.x4.shared.b16 {%0,%1,%2,%3}, [%4];"
                 : "=r"(a0), "=r"(a1), "=r"(a2), "=r"(a3) : "r"(addr));
}

__device__ __forceinline__ void stsm4(uint32_t addr, uint32_t x0, uint32_t x1,
                                      uint32_t x2, uint32_t x3) {
    asm volatile("stmatrix.sync.aligned.m8n8.x4.shared.b16 [%0], {%1,%2,%3,%4};"
                 :: "r"(addr), "r"(x0), "r"(x1), "r"(x2), "r"(x3) : "memory");
}

__device__ __forceinline__ void stsm4t(uint32_t addr, uint32_t x0, uint32_t x1,
                                       uint32_t x2, uint32_t x3) {
    asm volatile("stmatrix.sync.aligned.m8n8.x4.trans.shared.b16 [%0], {%1,%2,%3,%4};"
                 :: "r"(addr), "r"(x0), "r"(x1), "r"(x2), "r"(x3) : "memory");
}

__device__ __forceinline__ uint32_t packh2(float a, float b) {
    __half2 h = __floats2half2_rn(a, b);
    return *(uint32_t*)&h;
}

// ---------------- dense A build; zero stats ----------------
__global__ void k_graph(const void* __restrict__ ei_raw, int E) {
    __shared__ int   degs[NN];
    __shared__ float dinvs[NN];
    __shared__ int   is64;

    const int t = threadIdx.x;
    const int* e32 = (const int*)ei_raw;

    for (int i = t; i < 256 * 192; i += 256) g_Adense[i] = 0.f;
    if (t < LOWD) { g_sum1[t] = 0.f; g_sq1[t] = 0.f; }
    if (t < EMB)  { g_sum2[t] = 0.f; g_sq2[t] = 0.f; }

    if (t == 0) {
        int all0 = 1;
        int lim = 2 * E; if (lim > 512) lim = 512;
        for (int i = 1; i < lim; i += 2) if (e32[i] != 0) { all0 = 0; break; }
        is64 = all0;
    }
    if (t < NN) degs[t] = 1;
    __syncthreads();

    const long long* e64 = (const long long*)ei_raw;
    const int w64 = is64;

    for (int e = t; e < E; e += 256) {
        int d = w64 ? (int)e64[E + e] : e32[E + e];
        atomicAdd(&degs[d], 1);
    }
    __syncthreads();
    if (t < NN) dinvs[t] = rsqrtf((float)degs[t]);
    __syncthreads();
    for (int e = t; e < E; e += 256) {
        int s = w64 ? (int)e64[e] : e32[e];
        int d = w64 ? (int)e64[E + e] : e32[E + e];
        atomicAdd(&g_Adense[d * 192 + s], dinvs[s] * dinvs[d]);
    }
    if (t < NN)
        atomicAdd(&g_Adense[t * 192 + t], dinvs[t] * dinvs[t]);
}

// ---------------- column stats of low_dim_features ----------------
__global__ void k_stats1(const float* __restrict__ low, int B) {
    const int t = threadIdx.x;
    const int c = t & 63, rg = t >> 6;
    float s = 0.f, q = 0.f;
    for (int r = blockIdx.x * 4 + rg; r < B; r += gridDim.x * 4) {
        float v = low[r * LOWD + c];
        s += v; q += v * v;
    }
    __shared__ float ss[256], qq[256];
    ss[t] = s; qq[t] = q;
    __syncthreads();
    if (rg == 0) {
        atomicAdd(&g_sum1[c], ss[c] + ss[64 + c] + ss[128 + c] + ss[192 + c]);
        atomicAdd(&g_sq1[c],  qq[c] + qq[64 + c] + qq[128 + c] + qq[192 + c]);
    }
}

// ---------------- bn1 fold + linear + relu + bn2 stats ----------------
__global__ void __launch_bounds__(128) k_lowmlp(const float* __restrict__ low,
                                                const float* __restrict__ gbn, const float* __restrict__ bbn,
                                                const float* __restrict__ Wlow, const float* __restrict__ bllow,
                                                int B) {
    __shared__ float s1[LOWD], t1[LOWD];
    __shared__ float rows[8 * LOWD];
    const int t = threadIdx.x;

    if (t < LOWD) {
        float inv = 1.f / (float)B;
        float mu  = g_sum1[t] * inv;
        float var = g_sq1[t] * inv - mu * mu;
        float sc  = gbn[t] * rsqrtf(var + BEPS);
        s1[t] = sc;
        t1[t] = bbn[t] - mu * sc;
    }
    __syncthreads();

    float w[LOWD];
    float bias = bllow[t];
    #pragma unroll
    for (int k = 0; k < LOWD; k++) {
        float v = Wlow[k * EMB + t];
        w[k] = s1[k] * v;
        bias += t1[k] * v;
    }

    const int spb = (B + gridDim.x - 1) / gridDim.x;
    float ls = 0.f, lq = 0.f;
    const int r8 = t >> 4, q16 = t & 15;

    for (int it = 0; it < spb; it += 8) {
        int base = blockIdx.x * spb + it;
        int rrow = base + r8;
        if (rrow < B)
            ((float4*)rows)[t] = ((const float4*)low)[rrow * 16 + q16];
        __syncthreads();
        #pragma unroll
        for (int s = 0; s < 8; s++) {
            int r = base + s;
            if (r < B) {
                float acc = bias;
                const float4* rp = (const float4*)(rows + s * LOWD);
                #pragma unroll
                for (int k4 = 0; k4 < 16; k4++) {
                    float4 rv = rp[k4];
                    acc += rv.x * w[k4 * 4 + 0];
                    acc += rv.y * w[k4 * 4 + 1];
                    acc += rv.z * w[k4 * 4 + 2];
                    acc += rv.w * w[k4 * 4 + 3];
                }
                acc = fmaxf(acc, 0.f);
                g_relu_low[(size_t)r * EMB + t] = acc;
                ls += acc; lq += acc * acc;
            }
        }
        __syncthreads();
    }
    atomicAdd(&g_sum2[t], ls);
    atomicAdd(&g_sq2[t], lq);
}

// ---------------- persistent fused GCN: all three matmuls on HMMA ----------------
__global__ void __launch_bounds__(512) k_gcn(const float* __restrict__ high,
                                             const float* __restrict__ W1, const float* __restrict__ b1,
                                             const float* __restrict__ W2, const float* __restrict__ b2,
                                             int B) {
    extern __shared__ char sm[];
    const int t = threadIdx.x;
    const int lane = t & 31, w = t >> 5;
    const int g = lane >> 2, tig = lane & 3;
    const int n16 = (w & 3) * 16, mg = w >> 2;

    char* AD = sm + OFF_AD;
    char* WT = sm + OFF_WT;
    float* W1s  = (float*)(sm + OFF_W1);
    float* b1s  = (float*)(sm + OFF_B1);
    float* b2s  = (float*)(sm + OFF_B2);
    float* pool = (float*)(sm + OFF_POOL);

    const uint32_t sb = smem_u32(sm);

    // per-lane ldmatrix/stmatrix address bases
    const int lr = lane & 15, lc8 = (lane >> 4) * 8;
    const uint32_t aH1 = (uint32_t)(lr * 128 + lc8 * 2);   // + mt*2048 + kk*32, swz
    const uint32_t aAD = (uint32_t)(lr * 384 + lc8 * 2);   // + mt*6144 + kk*32, swz
    const int zrow = n16 + (lane & 7) + ((lane >> 4) << 3);
    const uint32_t aZT = (uint32_t)(zrow * 384 + ((lane & 8) ? 16 : 0));  // + kk*32 (ld) / + mt*32 (st)
    const uint32_t aXP = (uint32_t)(((lane & 7) + ((lane >> 4) << 3)) * 384 + ((lane & 8) ? 16 : 0));

    // ---- one-time images ----
    for (int i = t; i < 176 * 96; i += 512) {            // A_dense fp16 [176 x 192]
        int r = i / 96, cp = i % 96;
        float2 v = *(const float2*)(g_Adense + r * 192 + cp * 2);
        *(__half2*)(AD + swz((uint32_t)(r * 384 + cp * 4))) = __floats2half2_rn(v.x, v.y);
    }
    for (int i = t; i < 64 * 32; i += 512) {             // W2^T fp16 [64 x 64]
        int n = i >> 5, cp = i & 31;
        *(__half2*)(WT + swz((uint32_t)(n * 128 + cp * 4))) =
            __floats2half2_rn(W2[(2 * cp) * 64 + n], W2[(2 * cp + 1) * 64 + n]);
    }
    for (int i = t; i < 1536; i += 512)                  // zero XP (pads stay zero)
        ((uint32_t*)(sm + OFF_XP))[i] = 0;
    if (t < 192) W1s[t] = W1[t];
    if (t < 64) { b1s[t] = b1[t]; b2s[t] = b2[t]; }
    __syncthreads();

    // ---- W2 B-fragments preload (persistent) ----
    uint32_t wfr[4][2][2];
    #pragma unroll
    for (int kk = 0; kk < 4; kk++)
        #pragma unroll
        for (int s = 0; s < 2; s++) {
            int row = n16 + s * 8 + g;
            wfr[kk][s][0] = *(const uint32_t*)(WT + swz((uint32_t)(row * 128 + (kk * 16 + tig * 2) * 2)));
            wfr[kk][s][1] = *(const uint32_t*)(WT + swz((uint32_t)(row * 128 + (kk * 16 + tig * 2 + 8) * 2)));
        }

    // ---- W1 B-fragments (k=16 pad, only k<3 nonzero) ----
    uint32_t W1f[8];
    #pragma unroll
    for (int j = 0; j < 8; j++) {
        int n = j * 8 + g;
        float v0 = (2 * tig < 3)     ? W1s[(2 * tig) * 64 + n]     : 0.f;
        float v1 = (2 * tig + 1 < 3) ? W1s[(2 * tig + 1) * 64 + n] : 0.f;
        W1f[j] = packh2(v0, v1);
    }

    for (int b = blockIdx.x; b < B; b += gridDim.x) {
        // 1. zero pool; build XP image (x^T fp16) straight from gmem
        if (t < 64) pool[t] = 0.f;
        if (t < 498) {
            float v = high[(size_t)b * 498 + t];
            int k = t / 3, n = t - 3 * k;
            *(__half*)(sm + OFF_XP + swz((uint32_t)(n * 384 + k * 2))) = __float2half_rn(v);
        }
        __syncthreads();

        // 2. conv1 + h1 entirely on tensor cores (one m-tile per warp, w<11)
        if (w < 11) {
            const int mt = w;
            // y0 = A_dense @ x  (n=8, cols 0..2 valid)
            float y0a[4] = {0.f, 0.f, 0.f, 0.f};
            #pragma unroll
            for (int kk = 0; kk < 11; kk++) {
                uint32_t a0, a1, a2, a3, x0, x1, x2, x3;
                ldsm4(a0, a1, a2, a3, sb + OFF_AD + swz((uint32_t)(mt * 6144 + kk * 32) + aAD));
                ldsm4(x0, x1, x2, x3, sb + OFF_XP + swz(aXP + (uint32_t)(kk * 32)));
                mma8(y0a, a0, a1, a2, a3, x0, x1);
            }
            // h1 = relu(y0 @ W1 + b1): y0 accs ARE the A-fragment (k=16 pad)
            uint32_t ya0 = packh2(y0a[0], y0a[1]);
            uint32_t ya1 = packh2(y0a[2], y0a[3]);
            float hacc[32];
            #pragma unroll
            for (int i = 0; i < 32; i++) hacc[i] = 0.f;
            #pragma unroll
            for (int j = 0; j < 8; j++)
                mma8(hacc + j * 4, ya0, ya1, 0u, 0u, W1f[j], 0u);
            // bias + relu + stmatrix into H1
            const int q = lane >> 3, jr = lane & 7;
            #pragma unroll
            for (int ng = 0; ng < 4; ng++) {
                int j0 = 2 * ng, j1 = j0 + 1;
                float b00 = b1s[j0 * 8 + 2 * tig], b01 = b1s[j0 * 8 + 2 * tig + 1];
                float b10 = b1s[j1 * 8 + 2 * tig], b11 = b1s[j1 * 8 + 2 * tig + 1];
                uint32_t r0 = packh2(fmaxf(hacc[j0 * 4 + 0] + b00, 0.f), fmaxf(hacc[j0 * 4 + 1] + b01, 0.f));
                uint32_t r1 = packh2(fmaxf(hacc[j0 * 4 + 2] + b00, 0.f), fmaxf(hacc[j0 * 4 + 3] + b01, 0.f));
                uint32_t r2 = packh2(fmaxf(hacc[j1 * 4 + 0] + b10, 0.f), fmaxf(hacc[j1 * 4 + 1] + b11, 0.f));
                uint32_t r3 = packh2(fmaxf(hacc[j1 * 4 + 2] + b10, 0.f), fmaxf(hacc[j1 * 4 + 3] + b11, 0.f));
                int row = mt * 16 + ((q & 1) << 3) + jr;
                int col = ng * 16 + ((q & 2) << 2);
                stsm4(sb + OFF_H1 + swz((uint32_t)(row * 128 + col * 2)), r0, r1, r2, r3);
            }
        }
        __syncthreads();

        // 3. GEMM1: z = h1 @ W2 -> stmatrix.trans into z^T
        #pragma unroll
        for (int tt = 0; tt < 3; tt++) {
            int mt = mg + 4 * tt;
            if (mt < 11) {
                float z0[8] = {0, 0, 0, 0, 0, 0, 0, 0};
                #pragma unroll
                for (int kk = 0; kk < 4; kk++) {
                    uint32_t a0, a1, a2, a3;
                    ldsm4(a0, a1, a2, a3,
                          sb + OFF_H1 + swz((uint32_t)(mt * 2048 + kk * 32) + aH1));
                    mma8(z0,     a0, a1, a2, a3, wfr[kk][0][0], wfr[kk][0][1]);
                    mma8(z0 + 4, a0, a1, a2, a3, wfr[kk][1][0], wfr[kk][1][1]);
                }
                stsm4t(sb + OFF_ZT + swz(aZT + (uint32_t)(mt * 32)),
                       packh2(z0[0], z0[1]), packh2(z0[2], z0[3]),
                       packh2(z0[4], z0[5]), packh2(z0[6], z0[7]));
            }
        }
        __syncthreads();

        // 4. GEMM2: h2 = A_dense @ z ; fused bias+relu+pool
        uint32_t bfr[11][4];
        #pragma unroll
        for (int kk = 0; kk < 11; kk++)
            ldsm4(bfr[kk][0], bfr[kk][1], bfr[kk][2], bfr[kk][3],
                  sb + OFF_ZT + swz(aZT + (uint32_t)(kk * 32)));

        float pacc[4] = {0, 0, 0, 0};
        #pragma unroll
        for (int tt = 0; tt < 3; tt++) {
            int mt = mg + 4 * tt;
            if (mt < 11) {
                float dA[8] = {0, 0, 0, 0, 0, 0, 0, 0};
                float dB[8] = {0, 0, 0, 0, 0, 0, 0, 0};
                #pragma unroll
                for (int kk = 0; kk < 11; kk++) {
                    uint32_t a0, a1, a2, a3;
                    ldsm4(a0, a1, a2, a3,
                          sb + OFF_AD + swz((uint32_t)(mt * 6144 + kk * 32) + aAD));
                    float* dst = (kk & 1) ? dB : dA;
                    mma8(dst,     a0, a1, a2, a3, bfr[kk][0], bfr[kk][1]);
                    mma8(dst + 4, a0, a1, a2, a3, bfr[kk][2], bfr[kk][3]);
                }
                int m0 = mt * 16 + g;
                bool v0 = (m0 < NN), v1 = (m0 + 8 < NN);
                #pragma unroll
                for (int s = 0; s < 2; s++) {
                    int c = n16 + s * 8 + tig * 2;
                    float bb0 = b2s[c], bb1 = b2s[c + 1];
                    float e0 = dA[s * 4 + 0] + dB[s * 4 + 0];
                    float e1 = dA[s * 4 + 1] + dB[s * 4 + 1];
                    float e2 = dA[s * 4 + 2] + dB[s * 4 + 2];
                    float e3 = dA[s * 4 + 3] + dB[s * 4 + 3];
                    if (v0) {
                        pacc[s * 2]     += fmaxf(e0 + bb0, 0.f);
                        pacc[s * 2 + 1] += fmaxf(e1 + bb1, 0.f);
                    }
                    if (v1) {
                        pacc[s * 2]     += fmaxf(e2 + bb0, 0.f);
                        pacc[s * 2 + 1] += fmaxf(e3 + bb1, 0.f);
                    }
                }
            }
        }
        #pragma unroll
        for (int o = 4; o <= 16; o <<= 1) {
            pacc[0] += __shfl_xor_sync(0xffffffffu, pacc[0], o);
            pacc[1] += __shfl_xor_sync(0xffffffffu, pacc[1], o);
            pacc[2] += __shfl_xor_sync(0xffffffffu, pacc[2], o);
            pacc[3] += __shfl_xor_sync(0xffffffffu, pacc[3], o);
        }
        if (g == 0) {
            atomicAdd(&pool[n16 + tig * 2],         pacc[0]);
            atomicAdd(&pool[n16 + tig * 2 + 1],     pacc[1]);
            atomicAdd(&pool[n16 + 8 + tig * 2],     pacc[2]);
            atomicAdd(&pool[n16 + 8 + tig * 2 + 1], pacc[3]);
        }
        __syncthreads();
        if (t < 64) g_gfeat[(size_t)b * NC + t] = pool[t] * (1.f / (float)NN);
        __syncthreads();
    }
}

// ---------------- head: bn2 fold (local) + fc1 + relu + classifier + log_softmax ----------------
__global__ void __launch_bounds__(256) k_head(const float* __restrict__ Wfc1, const float* __restrict__ bfc1,
                                              const float* __restrict__ glow, const float* __restrict__ blow,
                                              const float* __restrict__ Wcls, const float* __restrict__ bcls,
                                              float* __restrict__ out, int B) {
    const int t = threadIdx.x;
    const int c = t & 127;
    const int kh = t >> 7;

    __shared__ float s2[EMB], t2[EMB];
    __shared__ float comb[FCIN];
    __shared__ float partial[2 * EMB];
    __shared__ float bfcs[EMB];
    __shared__ float wcl0[EMB], wcl1[EMB];
    __shared__ float red[8];

    if (t < EMB) {
        float inv = 1.f / (float)B;
        float mu  = g_sum2[t] * inv;
        float var = g_sq2[t] * inv - mu * mu;
        float sc  = glow[t] * rsqrtf(var + BEPS);
        s2[t] = sc;
        t2[t] = blow[t] - mu * sc;
    }
    __syncthreads();

    float w[96];
    #pragma unroll
    for (int i = 0; i < 96; i++) {
        int row = kh * 96 + i;
        float v = Wfc1[row * EMB + c];
        if (row >= NC) v *= s2[row - NC];
        w[i] = v;
    }
    if (t < EMB) {
        float acc = bfc1[t];
        for (int k = 0; k < EMB; k++) acc += t2[k] * Wfc1[(NC + k) * EMB + t];
        bfcs[t] = acc;
        wcl0[t] = Wcls[t * 2];
        wcl1[t] = Wcls[t * 2 + 1];
    }

    const int spb = (B + gridDim.x - 1) / gridDim.x;
    __syncthreads();

    for (int it = 0; it < spb; it++) {
        int s = blockIdx.x * spb + it;
        bool valid = (s < B);
        if (valid) {
            if (t < NC) comb[t] = g_gfeat[(size_t)s * NC + t];
            int u = t - NC;
            if (u >= 0 && u < EMB) comb[NC + u] = g_relu_low[(size_t)s * EMB + u];
        }
        __syncthreads();
        if (valid) {
            const float* cb = comb + kh * 96;
            float a0 = 0.f, a1 = 0.f, a2 = 0.f, a3 = 0.f;
            #pragma unroll
            for (int i = 0; i < 96; i += 4) {
                a0 += w[i] * cb[i];
                a1 += w[i + 1] * cb[i + 1];
                a2 += w[i + 2] * cb[i + 2];
                a3 += w[i + 3] * cb[i + 3];
            }
            partial[kh * EMB + c] = (a0 + a1) + (a2 + a3);
        }
        __syncthreads();
        if (valid && kh == 0) {
            float h = fmaxf(partial[c] + partial[EMB + c] + bfcs[c], 0.f);
            float p0 = h * wcl0[c];
            float p1 = h * wcl1[c];
            #pragma unroll
            for (int o = 16; o > 0; o >>= 1) {
                p0 += __shfl_down_sync(0xffffffffu, p0, o);
                p1 += __shfl_down_sync(0xffffffffu, p1, o);
            }
            if ((c & 31) == 0) { red[c >> 5] = p0; red[4 + (c >> 5)] = p1; }
        }
        __syncthreads();
        if (valid && t == 0) {
            float l0 = red[0] + red[1] + red[2] + red[3] + bcls[0];
            float l1 = red[4] + red[5] + red[6] + red[7] + bcls[1];
            float m = fmaxf(l0, l1);
            float lse = m + logf(expf(l0 - m) + expf(l1 - m));
            out[(size_t)s * 2 + 0] = l0 - lse;
            out[(size_t)s * 2 + 1] = l1 - lse;
        }
        __syncthreads();
    }
}

// ---------------- launch ----------------
extern "C" void kernel_launch(void* const* d_in, const int* in_sizes, int n_in,
                              void* d_out, int out_size) {
    const float* high  = (const float*)d_in[0];
    const float* low   = (const float*)d_in[1];
    const void*  ei    = d_in[2];
    const float* g_bn  = (const float*)d_in[3];
    const float* b_bn  = (const float*)d_in[4];
    const float* W_low = (const float*)d_in[5];
    const float* bl_lw = (const float*)d_in[6];
    const float* g_lo  = (const float*)d_in[7];
    const float* b_lo  = (const float*)d_in[8];
    const float* W1    = (const float*)d_in[9];
    const float* b1    = (const float*)d_in[10];
    const float* W2    = (const float*)d_in[11];
    const float* b2    = (const float*)d_in[12];
    const float* Wfc1  = (const float*)d_in[13];
    const float* bfc1  = (const float*)d_in[14];
    const float* Wcls  = (const float*)d_in[15];
    const float* bcls  = (const float*)d_in[16];

    int B = in_sizes[0] / (NN * 3);
    int E = in_sizes[2] / 2;
    float* out = (float*)d_out;

    k_graph<<<1, 256>>>(ei, E);
    k_stats1<<<64, 256>>>(low, B);
    k_lowmlp<<<256, 128>>>(low, g_bn, b_bn, W_low, bl_lw, B);

    cudaFuncSetAttribute(k_gcn, cudaFuncAttributeMaxDynamicSharedMemorySize, GCN_SMEM);
    int grid = 148;
    if (grid > B) grid = B;
    k_gcn<<<grid, 512, GCN_SMEM>>>(high, W1, b1, W2, b2, B);

    k_head<<<296, 256>>>(Wfc1, bfc1, g_lo, b_lo, Wcls, bcls, out, B);
}

// round 15
// speedup vs baseline: 1.6977x; 1.2653x over previous
#include <cuda_runtime.h>
#include <cuda_fp16.h>
#include <math.h>
#include <stdint.h>

#define NN   166
#define NC   64
#define EMB  128
#define LOWD 64
#define FCIN 192
#define BEPS 1e-5f
#define MAXB 8192

// ---- k_gcn smem layout (bytes); XP/WT/W1 overlay the ZT region ----
#define OFF_AD   0        // A_dense fp16 [176 x 192] swz      67584
#define OFF_H1   67584    // h1 fp16 [176 x 64] swz            22528
#define OFF_ZT   90112    // z^T fp16 [64 x 192] swz           24576
#define OFF_XP   90112    // overlay: x^T fp16 [16 x 192] swz   6144 (per-sample)
#define OFF_WT   96256    // overlay: W2^T fp16 [64x64] swz     8192 (init only)
#define OFF_W1   104448   // overlay: W1 fp32 (192)              768 (init only)
#define OFF_B1   114688   // b1 fp32 (64)
#define OFF_B2   114944   // b2 fp32 (64)
#define OFF_POOL 115200   // pool fp32 (64)
#define GCN_SMEM 115456

// ---------------- device scratch ----------------
__device__ float g_Adense[256 * 192];
__device__ float g_sum1[LOWD], g_sq1[LOWD];
__device__ float g_sum2[EMB],  g_sq2[EMB];
__device__ float g_relu_low[MAXB * EMB];
__device__ float g_gfeat[MAXB * NC];

// ---------------- helpers ----------------
__device__ __forceinline__ uint32_t swz(uint32_t o) { return o ^ ((o >> 3) & 0x70); }

__device__ __forceinline__ uint32_t smem_u32(const void* p) {
    uint32_t a;
    asm("{ .reg .u64 t; cvta.to.shared.u64 t, %1; cvt.u32.u64 %0, t; }" : "=r"(a) : "l"(p));
    return a;
}

__device__ __forceinline__ void mma8(float* d, uint32_t a0, uint32_t a1, uint32_t a2, uint32_t a3,
                                     uint32_t b0, uint32_t b1) {
    asm volatile(
        "mma.sync.aligned.m16n8k16.row.col.f32.f16.f16.f32 "
        "{%0,%1,%2,%3}, {%4,%5,%6,%7}, {%8,%9}, {%0,%1,%2,%3};"
        : "+f"(d[0]), "+f"(d[1]), "+f"(d[2]), "+f"(d[3])
        : "r"(a0), "r"(a1), "r"(a2), "r"(a3), "r"(b0), "r"(b1));
}

__device__ __forceinline__ void ldsm4(uint32_t& a0, uint32_t& a1, uint32_t& a2, uint32_t& a3,
                                      uint32_t addr) {
    asm volatile("ldmatrix.sync.aligned.m8n8.x4.shared.b16 {%0,%1,%2,%3}, [%4];"
                 : "=r"(a0), "=r"(a1), "=r"(a2), "=r"(a3) : "r"(addr));
}

__device__ __forceinline__ void stsm4(uint32_t addr, uint32_t x0, uint32_t x1,
                                      uint32_t x2, uint32_t x3) {
    asm volatile("stmatrix.sync.aligned.m8n8.x4.shared.b16 [%0], {%1,%2,%3,%4};"
                 :: "r"(addr), "r"(x0), "r"(x1), "r"(x2), "r"(x3) : "memory");
}

__device__ __forceinline__ void stsm4t(uint32_t addr, uint32_t x0, uint32_t x1,
                                       uint32_t x2, uint32_t x3) {
    asm volatile("stmatrix.sync.aligned.m8n8.x4.trans.shared.b16 [%0], {%1,%2,%3,%4};"
                 :: "r"(addr), "r"(x0), "r"(x1), "r"(x2), "r"(x3) : "memory");
}

__device__ __forceinline__ uint32_t packh2(float a, float b) {
    __half2 h = __floats2half2_rn(a, b);
    return *(uint32_t*)&h;
}

// ---------------- dense A build; zero stats ----------------
__global__ void k_graph(const void* __restrict__ ei_raw, int E) {
    __shared__ int   degs[NN];
    __shared__ float dinvs[NN];
    __shared__ int   is64;

    const int t = threadIdx.x;
    const int* e32 = (const int*)ei_raw;

    for (int i = t; i < 256 * 192; i += 256) g_Adense[i] = 0.f;
    if (t < LOWD) { g_sum1[t] = 0.f; g_sq1[t] = 0.f; }
    if (t < EMB)  { g_sum2[t] = 0.f; g_sq2[t] = 0.f; }

    if (t == 0) {
        int all0 = 1;
        int lim = 2 * E; if (lim > 512) lim = 512;
        for (int i = 1; i < lim; i += 2) if (e32[i] != 0) { all0 = 0; break; }
        is64 = all0;
    }
    if (t < NN) degs[t] = 1;
    __syncthreads();

    const long long* e64 = (const long long*)ei_raw;
    const int w64 = is64;

    for (int e = t; e < E; e += 256) {
        int d = w64 ? (int)e64[E + e] : e32[E + e];
        atomicAdd(&degs[d], 1);
    }
    __syncthreads();
    if (t < NN) dinvs[t] = rsqrtf((float)degs[t]);
    __syncthreads();
    for (int e = t; e < E; e += 256) {
        int s = w64 ? (int)e64[e] : e32[e];
        int d = w64 ? (int)e64[E + e] : e32[E + e];
        atomicAdd(&g_Adense[d * 192 + s], dinvs[s] * dinvs[d]);
    }
    if (t < NN)
        atomicAdd(&g_Adense[t * 192 + t], dinvs[t] * dinvs[t]);
}

// ---------------- column stats of low_dim_features ----------------
__global__ void k_stats1(const float* __restrict__ low, int B) {
    const int t = threadIdx.x;
    const int c = t & 63, rg = t >> 6;
    float s = 0.f, q = 0.f;
    for (int r = blockIdx.x * 4 + rg; r < B; r += gridDim.x * 4) {
        float v = low[r * LOWD + c];
        s += v; q += v * v;
    }
    __shared__ float ss[256], qq[256];
    ss[t] = s; qq[t] = q;
    __syncthreads();
    if (rg == 0) {
        atomicAdd(&g_sum1[c], ss[c] + ss[64 + c] + ss[128 + c] + ss[192 + c]);
        atomicAdd(&g_sq1[c],  qq[c] + qq[64 + c] + qq[128 + c] + qq[192 + c]);
    }
}

// ---------------- bn1 fold + linear + relu + bn2 stats ----------------
__global__ void __launch_bounds__(128) k_lowmlp(const float* __restrict__ low,
                                                const float* __restrict__ gbn, const float* __restrict__ bbn,
                                                const float* __restrict__ Wlow, const float* __restrict__ bllow,
                                                int B) {
    __shared__ float s1[LOWD], t1[LOWD];
    __shared__ float rows[8 * LOWD];
    const int t = threadIdx.x;

    if (t < LOWD) {
        float inv = 1.f / (float)B;
        float mu  = g_sum1[t] * inv;
        float var = g_sq1[t] * inv - mu * mu;
        float sc  = gbn[t] * rsqrtf(var + BEPS);
        s1[t] = sc;
        t1[t] = bbn[t] - mu * sc;
    }
    __syncthreads();

    float w[LOWD];
    float bias = bllow[t];
    #pragma unroll
    for (int k = 0; k < LOWD; k++) {
        float v = Wlow[k * EMB + t];
        w[k] = s1[k] * v;
        bias += t1[k] * v;
    }

    const int spb = (B + gridDim.x - 1) / gridDim.x;
    float ls = 0.f, lq = 0.f;
    const int r8 = t >> 4, q16 = t & 15;

    for (int it = 0; it < spb; it += 8) {
        int base = blockIdx.x * spb + it;
        int rrow = base + r8;
        if (rrow < B)
            ((float4*)rows)[t] = ((const float4*)low)[rrow * 16 + q16];
        __syncthreads();
        #pragma unroll
        for (int s = 0; s < 8; s++) {
            int r = base + s;
            if (r < B) {
                float acc = bias;
                const float4* rp = (const float4*)(rows + s * LOWD);
                #pragma unroll
                for (int k4 = 0; k4 < 16; k4++) {
                    float4 rv = rp[k4];
                    acc += rv.x * w[k4 * 4 + 0];
                    acc += rv.y * w[k4 * 4 + 1];
                    acc += rv.z * w[k4 * 4 + 2];
                    acc += rv.w * w[k4 * 4 + 3];
                }
                acc = fmaxf(acc, 0.f);
                g_relu_low[(size_t)r * EMB + t] = acc;
                ls += acc; lq += acc * acc;
            }
        }
        __syncthreads();
    }
    atomicAdd(&g_sum2[t], ls);
    atomicAdd(&g_sq2[t], lq);
}

// ---------------- persistent fused GCN: all-HMMA, 256 thr x 2 CTAs/SM ----------------
__global__ void __launch_bounds__(256, 2) k_gcn(const float* __restrict__ high,
                                                const float* __restrict__ W1, const float* __restrict__ b1,
                                                const float* __restrict__ W2, const float* __restrict__ b2,
                                                int B) {
    extern __shared__ char sm[];
    const int t = threadIdx.x;
    const int lane = t & 31, w = t >> 5;      // 8 warps
    const int g = lane >> 2, tig = lane & 3;
    const int n16 = (w & 3) * 16, mg = w >> 2;   // mg 0..1

    char* AD = sm + OFF_AD;
    char* WT = sm + OFF_WT;
    float* W1s  = (float*)(sm + OFF_W1);
    float* b1s  = (float*)(sm + OFF_B1);
    float* b2s  = (float*)(sm + OFF_B2);
    float* pool = (float*)(sm + OFF_POOL);

    const uint32_t sb = smem_u32(sm);

    // per-lane ldmatrix/stmatrix address bases
    const int lr = lane & 15, lc8 = (lane >> 4) * 8;
    const uint32_t aH1 = (uint32_t)(lr * 128 + lc8 * 2);   // + mt*2048 + kk*32, swz
    const uint32_t aAD = (uint32_t)(lr * 384 + lc8 * 2);   // + mt*6144 + kk*32, swz
    const int zrow = n16 + (lane & 7) + ((lane >> 4) << 3);
    const uint32_t aZT = (uint32_t)(zrow * 384 + ((lane & 8) ? 16 : 0));  // + kk*32 (ld) / + mt*32 (st)
    const uint32_t aXP = (uint32_t)(((lane & 7) + ((lane >> 4) << 3)) * 384 + ((lane & 8) ? 16 : 0));

    // ---- one-time images (WT/W1s live in the ZT overlay until fragments are built) ----
    for (int i = t; i < 176 * 96; i += 256) {            // A_dense fp16 [176 x 192]
        int r = i / 96, cp = i % 96;
        float2 v = *(const float2*)(g_Adense + r * 192 + cp * 2);
        *(__half2*)(AD + swz((uint32_t)(r * 384 + cp * 4))) = __floats2half2_rn(v.x, v.y);
    }
    for (int i = t; i < 64 * 32; i += 256) {             // W2^T fp16 [64 x 64]
        int n = i >> 5, cp = i & 31;
        *(__half2*)(WT + swz((uint32_t)(n * 128 + cp * 4))) =
            __floats2half2_rn(W2[(2 * cp) * 64 + n], W2[(2 * cp + 1) * 64 + n]);
    }
    if (t < 192) W1s[t] = W1[t];
    if (t < 64) { b1s[t] = b1[t]; b2s[t] = b2[t]; }
    __syncthreads();

    // ---- W2 B-fragments preload (persistent; WT dead afterwards) ----
    uint32_t wfr[4][2][2];
    #pragma unroll
    for (int kk = 0; kk < 4; kk++)
        #pragma unroll
        for (int s = 0; s < 2; s++) {
            int row = n16 + s * 8 + g;
            wfr[kk][s][0] = *(const uint32_t*)(WT + swz((uint32_t)(row * 128 + (kk * 16 + tig * 2) * 2)));
            wfr[kk][s][1] = *(const uint32_t*)(WT + swz((uint32_t)(row * 128 + (kk * 16 + tig * 2 + 8) * 2)));
        }

    // ---- W1 B-fragments (k=16 pad, only k<3 nonzero; W1s dead afterwards) ----
    uint32_t W1f[8];
    #pragma unroll
    for (int j = 0; j < 8; j++) {
        int n = j * 8 + g;
        float v0 = (2 * tig < 3)     ? W1s[(2 * tig) * 64 + n]     : 0.f;
        float v1 = (2 * tig + 1 < 3) ? W1s[(2 * tig + 1) * 64 + n] : 0.f;
        W1f[j] = packh2(v0, v1);
    }
    __syncthreads();

    for (int b = blockIdx.x; b < B; b += gridDim.x) {
        // 1. zero pool; rebuild full XP image (x^T fp16, pads zeroed) from gmem
        if (t < 64) pool[t] = 0.f;
        for (int i = t; i < 16 * 192; i += 256) {
            int n = i / 192, k = i - n * 192;
            float v = (n < 3 && k < NN) ? high[(size_t)b * 498 + k * 3 + n] : 0.f;
            *(__half*)(sm + OFF_XP + swz((uint32_t)(n * 384 + k * 2))) = __float2half_rn(v);
        }
        __syncthreads();

        // 2. conv1 + h1 on tensor cores (warp handles mt = w, w+8)
        for (int mt = w; mt < 11; mt += 8) {
            float y0a[4] = {0.f, 0.f, 0.f, 0.f};
            #pragma unroll
            for (int kk = 0; kk < 11; kk++) {
                uint32_t a0, a1, a2, a3, x0, x1, x2, x3;
                ldsm4(a0, a1, a2, a3, sb + OFF_AD + swz((uint32_t)(mt * 6144 + kk * 32) + aAD));
                ldsm4(x0, x1, x2, x3, sb + OFF_XP + swz(aXP + (uint32_t)(kk * 32)));
                mma8(y0a, a0, a1, a2, a3, x0, x1);
            }
            uint32_t ya0 = packh2(y0a[0], y0a[1]);
            uint32_t ya1 = packh2(y0a[2], y0a[3]);
            float hacc[32];
            #pragma unroll
            for (int i = 0; i < 32; i++) hacc[i] = 0.f;
            #pragma unroll
            for (int j = 0; j < 8; j++)
                mma8(hacc + j * 4, ya0, ya1, 0u, 0u, W1f[j], 0u);
            const int q = lane >> 3, jr = lane & 7;
            #pragma unroll
            for (int ng = 0; ng < 4; ng++) {
                int j0 = 2 * ng, j1 = j0 + 1;
                float b00 = b1s[j0 * 8 + 2 * tig], b01 = b1s[j0 * 8 + 2 * tig + 1];
                float b10 = b1s[j1 * 8 + 2 * tig], b11 = b1s[j1 * 8 + 2 * tig + 1];
                uint32_t r0 = packh2(fmaxf(hacc[j0 * 4 + 0] + b00, 0.f), fmaxf(hacc[j0 * 4 + 1] + b01, 0.f));
                uint32_t r1 = packh2(fmaxf(hacc[j0 * 4 + 2] + b00, 0.f), fmaxf(hacc[j0 * 4 + 3] + b01, 0.f));
                uint32_t r2 = packh2(fmaxf(hacc[j1 * 4 + 0] + b10, 0.f), fmaxf(hacc[j1 * 4 + 1] + b11, 0.f));
                uint32_t r3 = packh2(fmaxf(hacc[j1 * 4 + 2] + b10, 0.f), fmaxf(hacc[j1 * 4 + 3] + b11, 0.f));
                int row = mt * 16 + ((q & 1) << 3) + jr;
                int col = ng * 16 + ((q & 2) << 2);
                stsm4(sb + OFF_H1 + swz((uint32_t)(row * 128 + col * 2)), r0, r1, r2, r3);
            }
        }
        __syncthreads();

        // 3. GEMM1: z = h1 @ W2 -> stmatrix.trans into z^T (stomps XP overlay; XP dead)
        #pragma unroll
        for (int tt = 0; tt < 6; tt++) {
            int mt = mg + 2 * tt;
            if (mt < 11) {
                float z0[8] = {0, 0, 0, 0, 0, 0, 0, 0};
                #pragma unroll
                for (int kk = 0; kk < 4; kk++) {
                    uint32_t a0, a1, a2, a3;
                    ldsm4(a0, a1, a2, a3,
                          sb + OFF_H1 + swz((uint32_t)(mt * 2048 + kk * 32) + aH1));
                    mma8(z0,     a0, a1, a2, a3, wfr[kk][0][0], wfr[kk][0][1]);
                    mma8(z0 + 4, a0, a1, a2, a3, wfr[kk][1][0], wfr[kk][1][1]);
                }
                stsm4t(sb + OFF_ZT + swz(aZT + (uint32_t)(mt * 32)),
                       packh2(z0[0], z0[1]), packh2(z0[2], z0[3]),
                       packh2(z0[4], z0[5]), packh2(z0[6], z0[7]));
            }
        }
        __syncthreads();

        // 4. GEMM2: h2 = A_dense @ z ; fused bias+relu+pool
        uint32_t bfr[11][4];
        #pragma unroll
        for (int kk = 0; kk < 11; kk++)
            ldsm4(bfr[kk][0], bfr[kk][1], bfr[kk][2], bfr[kk][3],
                  sb + OFF_ZT + swz(aZT + (uint32_t)(kk * 32)));

        float pacc[4] = {0, 0, 0, 0};
        #pragma unroll
        for (int tt = 0; tt < 6; tt++) {
            int mt = mg + 2 * tt;
            if (mt < 11) {
                float dA[8] = {0, 0, 0, 0, 0, 0, 0, 0};
                float dB[8] = {0, 0, 0, 0, 0, 0, 0, 0};
                #pragma unroll
                for (int kk = 0; kk < 11; kk++) {
                    uint32_t a0, a1, a2, a3;
                    ldsm4(a0, a1, a2, a3,
                          sb + OFF_AD + swz((uint32_t)(mt * 6144 + kk * 32) + aAD));
                    float* dst = (kk & 1) ? dB : dA;
                    mma8(dst,     a0, a1, a2, a3, bfr[kk][0], bfr[kk][1]);
                    mma8(dst + 4, a0, a1, a2, a3, bfr[kk][2], bfr[kk][3]);
                }
                int m0 = mt * 16 + g;
                bool v0 = (m0 < NN), v1 = (m0 + 8 < NN);
                #pragma unroll
                for (int s = 0; s < 2; s++) {
                    int c = n16 + s * 8 + tig * 2;
                    float bb0 = b2s[c], bb1 = b2s[c + 1];
                    float e0 = dA[s * 4 + 0] + dB[s * 4 + 0];
                    float e1 = dA[s * 4 + 1] + dB[s * 4 + 1];
                    float e2 = dA[s * 4 + 2] + dB[s * 4 + 2];
                    float e3 = dA[s * 4 + 3] + dB[s * 4 + 3];
                    if (v0) {
                        pacc[s * 2]     += fmaxf(e0 + bb0, 0.f);
                        pacc[s * 2 + 1] += fmaxf(e1 + bb1, 0.f);
                    }
                    if (v1) {
                        pacc[s * 2]     += fmaxf(e2 + bb0, 0.f);
                        pacc[s * 2 + 1] += fmaxf(e3 + bb1, 0.f);
                    }
                }
            }
        }
        #pragma unroll
        for (int o = 4; o <= 16; o <<= 1) {
            pacc[0] += __shfl_xor_sync(0xffffffffu, pacc[0], o);
            pacc[1] += __shfl_xor_sync(0xffffffffu, pacc[1], o);
            pacc[2] += __shfl_xor_sync(0xffffffffu, pacc[2], o);
            pacc[3] += __shfl_xor_sync(0xffffffffu, pacc[3], o);
        }
        if (g == 0) {
            atomicAdd(&pool[n16 + tig * 2],         pacc[0]);
            atomicAdd(&pool[n16 + tig * 2 + 1],     pacc[1]);
            atomicAdd(&pool[n16 + 8 + tig * 2],     pacc[2]);
            atomicAdd(&pool[n16 + 8 + tig * 2 + 1], pacc[3]);
        }
        __syncthreads();
        if (t < 64) g_gfeat[(size_t)b * NC + t] = pool[t] * (1.f / (float)NN);
        __syncthreads();
    }
}

// ---------------- head: bn2 fold (local) + fc1 + relu + classifier + log_softmax ----------------
__global__ void __launch_bounds__(256) k_head(const float* __restrict__ Wfc1, const float* __restrict__ bfc1,
                                              const float* __restrict__ glow, const float* __restrict__ blow,
                                              const float* __restrict__ Wcls, const float* __restrict__ bcls,
                                              float* __restrict__ out, int B) {
    const int t = threadIdx.x;
    const int c = t & 127;
    const int kh = t >> 7;

    __shared__ float s2[EMB], t2[EMB];
    __shared__ float comb[FCIN];
    __shared__ float partial[2 * EMB];
    __shared__ float bfcs[EMB];
    __shared__ float wcl0[EMB], wcl1[EMB];
    __shared__ float red[8];

    if (t < EMB) {
        float inv = 1.f / (float)B;
        float mu  = g_sum2[t] * inv;
        float var = g_sq2[t] * inv - mu * mu;
        float sc  = glow[t] * rsqrtf(var + BEPS);
        s2[t] = sc;
        t2[t] = blow[t] - mu * sc;
    }
    __syncthreads();

    float w[96];
    #pragma unroll
    for (int i = 0; i < 96; i++) {
        int row = kh * 96 + i;
        float v = Wfc1[row * EMB + c];
        if (row >= NC) v *= s2[row - NC];
        w[i] = v;
    }
    if (t < EMB) {
        float acc = bfc1[t];
        for (int k = 0; k < EMB; k++) acc += t2[k] * Wfc1[(NC + k) * EMB + t];
        bfcs[t] = acc;
        wcl0[t] = Wcls[t * 2];
        wcl1[t] = Wcls[t * 2 + 1];
    }

    const int spb = (B + gridDim.x - 1) / gridDim.x;
    __syncthreads();

    for (int it = 0; it < spb; it++) {
        int s = blockIdx.x * spb + it;
        bool valid = (s < B);
        if (valid) {
            if (t < NC) comb[t] = g_gfeat[(size_t)s * NC + t];
            int u = t - NC;
            if (u >= 0 && u < EMB) comb[NC + u] = g_relu_low[(size_t)s * EMB + u];
        }
        __syncthreads();
        if (valid) {
            const float* cb = comb + kh * 96;
            float a0 = 0.f, a1 = 0.f, a2 = 0.f, a3 = 0.f;
            #pragma unroll
            for (int i = 0; i < 96; i += 4) {
                a0 += w[i] * cb[i];
                a1 += w[i + 1] * cb[i + 1];
                a2 += w[i + 2] * cb[i + 2];
                a3 += w[i + 3] * cb[i + 3];
            }
            partial[kh * EMB + c] = (a0 + a1) + (a2 + a3);
        }
        __syncthreads();
        if (valid && kh == 0) {
            float h = fmaxf(partial[c] + partial[EMB + c] + bfcs[c], 0.f);
            float p0 = h * wcl0[c];
            float p1 = h * wcl1[c];
            #pragma unroll
            for (int o = 16; o > 0; o >>= 1) {
                p0 += __shfl_down_sync(0xffffffffu, p0, o);
                p1 += __shfl_down_sync(0xffffffffu, p1, o);
            }
            if ((c & 31) == 0) { red[c >> 5] = p0; red[4 + (c >> 5)] = p1; }
        }
        __syncthreads();
        if (valid && t == 0) {
            float l0 = red[0] + red[1] + red[2] + red[3] + bcls[0];
            float l1 = red[4] + red[5] + red[6] + red[7] + bcls[1];
            float m = fmaxf(l0, l1);
            float lse = m + logf(expf(l0 - m) + expf(l1 - m));
            out[(size_t)s * 2 + 0] = l0 - lse;
            out[(size_t)s * 2 + 1] = l1 - lse;
        }
        __syncthreads();
    }
}

// ---------------- launch ----------------
extern "C" void kernel_launch(void* const* d_in, const int* in_sizes, int n_in,
                              void* d_out, int out_size) {
    const float* high  = (const float*)d_in[0];
    const float* low   = (const float*)d_in[1];
    const void*  ei    = d_in[2];
    const float* g_bn  = (const float*)d_in[3];
    const float* b_bn  = (const float*)d_in[4];
    const float* W_low = (const float*)d_in[5];
    const float* bl_lw = (const float*)d_in[6];
    const float* g_lo  = (const float*)d_in[7];
    const float* b_lo  = (const float*)d_in[8];
    const float* W1    = (const float*)d_in[9];
    const float* b1    = (const float*)d_in[10];
    const float* W2    = (const float*)d_in[11];
    const float* b2    = (const float*)d_in[12];
    const float* Wfc1  = (const float*)d_in[13];
    const float* bfc1  = (const float*)d_in[14];
    const float* Wcls  = (const float*)d_in[15];
    const float* bcls  = (const float*)d_in[16];

    int B = in_sizes[0] / (NN * 3);
    int E = in_sizes[2] / 2;
    float* out = (float*)d_out;

    k_graph<<<1, 256>>>(ei, E);
    k_stats1<<<64, 256>>>(low, B);
    k_lowmlp<<<256, 128>>>(low, g_bn, b_bn, W_low, bl_lw, B);

    cudaFuncSetAttribute(k_gcn, cudaFuncAttributeMaxDynamicSharedMemorySize, GCN_SMEM);
    int grid = 296;
    if (grid > B) grid = B;
    k_gcn<<<grid, 256, GCN_SMEM>>>(high, W1, b1, W2, b2, B);

    k_head<<<296, 256>>>(Wfc1, bfc1, g_lo, b_lo, Wcls, bcls, out, B);
}

// round 16
// speedup vs baseline: 1.8047x; 1.0630x over previous
#include <cuda_runtime.h>
#include <cuda_fp16.h>
#include <math.h>
#include <stdint.h>

#define NN   166
#define NC   64
#define EMB  128
#define LOWD 64
#define FCIN 192
#define BEPS 1e-5f
#define MAXB 8192

// ---- k_gcn smem layout (bytes); no overlays, H1 eliminated ----
#define OFF_AD   0        // A_dense fp16 [176 x 192] swz      67584
#define OFF_XP   67584    // x^T fp16 [16 x 192] swz (persistent) 6144
#define OFF_ZT   73728    // z^T fp16 [64 x 192] swz           24576
#define OFF_WT   98304    // W2^T fp16 [64 x 64] swz            8192
#define OFF_W1T  106496   // packed W1 B-frag table [8][32] u32 1024
#define OFF_B1   107520   // b1 fp32 (64)
#define OFF_B2   107776   // b2 fp32 (64)
#define OFF_POOL 108032   // pool fp32 (64)
#define GCN_SMEM 108288

// ---------------- device scratch ----------------
__device__ float g_Adense[256 * 192];
__device__ float g_sum1[LOWD], g_sq1[LOWD];
__device__ float g_sum2[EMB],  g_sq2[EMB];
__device__ float g_relu_low[MAXB * EMB];
__device__ float g_gfeat[MAXB * NC];

// ---------------- helpers ----------------
__device__ __forceinline__ uint32_t swz(uint32_t o) { return o ^ ((o >> 3) & 0x70); }

__device__ __forceinline__ uint32_t smem_u32(const void* p) {
    uint32_t a;
    asm("{ .reg .u64 t; cvta.to.shared.u64 t, %1; cvt.u32.u64 %0, t; }" : "=r"(a) : "l"(p));
    return a;
}

__device__ __forceinline__ void mma8(float* d, uint32_t a0, uint32_t a1, uint32_t a2, uint32_t a3,
                                     uint32_t b0, uint32_t b1) {
    asm volatile(
        "mma.sync.aligned.m16n8k16.row.col.f32.f16.f16.f32 "
        "{%0,%1,%2,%3}, {%4,%5,%6,%7}, {%8,%9}, {%0,%1,%2,%3};"
        : "+f"(d[0]), "+f"(d[1]), "+f"(d[2]), "+f"(d[3])
        : "r"(a0), "r"(a1), "r"(a2), "r"(a3), "r"(b0), "r"(b1));
}

__device__ __forceinline__ void ldsm4(uint32_t& a0, uint32_t& a1, uint32_t& a2, uint32_t& a3,
                                      uint32_t addr) {
    asm volatile("ldmatrix.sync.aligned.m8n8.x4.shared.b16 {%0,%1,%2,%3}, [%4];"
                 : "=r"(a0), "=r"(a1), "=r"(a2), "=r"(a3) : "r"(addr));
}

__device__ __forceinline__ void ldsm2(uint32_t& a0, uint32_t& a1, uint32_t addr) {
    asm volatile("ldmatrix.sync.aligned.m8n8.x2.shared.b16 {%0,%1}, [%2];"
                 : "=r"(a0), "=r"(a1) : "r"(addr));
}

__device__ __forceinline__ void stsm4t(uint32_t addr, uint32_t x0, uint32_t x1,
                                       uint32_t x2, uint32_t x3) {
    asm volatile("stmatrix.sync.aligned.m8n8.x4.trans.shared.b16 [%0], {%1,%2,%3,%4};"
                 :: "r"(addr), "r"(x0), "r"(x1), "r"(x2), "r"(x3) : "memory");
}

__device__ __forceinline__ uint32_t packh2(float a, float b) {
    __half2 h = __floats2half2_rn(a, b);
    return *(uint32_t*)&h;
}

// ---------------- dense A build; zero stats ----------------
__global__ void k_graph(const void* __restrict__ ei_raw, int E) {
    __shared__ int   degs[NN];
    __shared__ float dinvs[NN];
    __shared__ int   is64;

    const int t = threadIdx.x;
    const int* e32 = (const int*)ei_raw;

    for (int i = t; i < 256 * 192; i += 256) g_Adense[i] = 0.f;
    if (t < LOWD) { g_sum1[t] = 0.f; g_sq1[t] = 0.f; }
    if (t < EMB)  { g_sum2[t] = 0.f; g_sq2[t] = 0.f; }

    if (t == 0) {
        int all0 = 1;
        int lim = 2 * E; if (lim > 512) lim = 512;
        for (int i = 1; i < lim; i += 2) if (e32[i] != 0) { all0 = 0; break; }
        is64 = all0;
    }
    if (t < NN) degs[t] = 1;
    __syncthreads();

    const long long* e64 = (const long long*)ei_raw;
    const int w64 = is64;

    for (int e = t; e < E; e += 256) {
        int d = w64 ? (int)e64[E + e] : e32[E + e];
        atomicAdd(&degs[d], 1);
    }
    __syncthreads();
    if (t < NN) dinvs[t] = rsqrtf((float)degs[t]);
    __syncthreads();
    for (int e = t; e < E; e += 256) {
        int s = w64 ? (int)e64[e] : e32[e];
        int d = w64 ? (int)e64[E + e] : e32[E + e];
        atomicAdd(&g_Adense[d * 192 + s], dinvs[s] * dinvs[d]);
    }
    if (t < NN)
        atomicAdd(&g_Adense[t * 192 + t], dinvs[t] * dinvs[t]);
}

// ---------------- column stats of low_dim_features ----------------
__global__ void k_stats1(const float* __restrict__ low, int B) {
    const int t = threadIdx.x;
    const int c = t & 63, rg = t >> 6;
    float s = 0.f, q = 0.f;
    for (int r = blockIdx.x * 4 + rg; r < B; r += gridDim.x * 4) {
        float v = low[r * LOWD + c];
        s += v; q += v * v;
    }
    __shared__ float ss[256], qq[256];
    ss[t] = s; qq[t] = q;
    __syncthreads();
    if (rg == 0) {
        atomicAdd(&g_sum1[c], ss[c] + ss[64 + c] + ss[128 + c] + ss[192 + c]);
        atomicAdd(&g_sq1[c],  qq[c] + qq[64 + c] + qq[128 + c] + qq[192 + c]);
    }
}

// ---------------- bn1 fold + linear + relu + bn2 stats ----------------
__global__ void __launch_bounds__(128) k_lowmlp(const float* __restrict__ low,
                                                const float* __restrict__ gbn, const float* __restrict__ bbn,
                                                const float* __restrict__ Wlow, const float* __restrict__ bllow,
                                                int B) {
    __shared__ float s1[LOWD], t1[LOWD];
    __shared__ float rows[8 * LOWD];
    const int t = threadIdx.x;

    if (t < LOWD) {
        float inv = 1.f / (float)B;
        float mu  = g_sum1[t] * inv;
        float var = g_sq1[t] * inv - mu * mu;
        float sc  = gbn[t] * rsqrtf(var + BEPS);
        s1[t] = sc;
        t1[t] = bbn[t] - mu * sc;
    }
    __syncthreads();

    float w[LOWD];
    float bias = bllow[t];
    #pragma unroll
    for (int k = 0; k < LOWD; k++) {
        float v = Wlow[k * EMB + t];
        w[k] = s1[k] * v;
        bias += t1[k] * v;
    }

    const int spb = (B + gridDim.x - 1) / gridDim.x;
    float ls = 0.f, lq = 0.f;
    const int r8 = t >> 4, q16 = t & 15;

    for (int it = 0; it < spb; it += 8) {
        int base = blockIdx.x * spb + it;
        int rrow = base + r8;
        if (rrow < B)
            ((float4*)rows)[t] = ((const float4*)low)[rrow * 16 + q16];
        __syncthreads();
        #pragma unroll
        for (int s = 0; s < 8; s++) {
            int r = base + s;
            if (r < B) {
                float acc = bias;
                const float4* rp = (const float4*)(rows + s * LOWD);
                #pragma unroll
                for (int k4 = 0; k4 < 16; k4++) {
                    float4 rv = rp[k4];
                    acc += rv.x * w[k4 * 4 + 0];
                    acc += rv.y * w[k4 * 4 + 1];
                    acc += rv.z * w[k4 * 4 + 2];
                    acc += rv.w * w[k4 * 4 + 3];
                }
                acc = fmaxf(acc, 0.f);
                g_relu_low[(size_t)r * EMB + t] = acc;
                ls += acc; lq += acc * acc;
            }
        }
        __syncthreads();
    }
    atomicAdd(&g_sum2[t], ls);
    atomicAdd(&g_sq2[t], lq);
}

// ---------------- persistent fused GCN: conv1+GEMM1 in registers, no H1 image ----------------
__global__ void __launch_bounds__(256, 2) k_gcn(const float* __restrict__ high,
                                                const float* __restrict__ W1, const float* __restrict__ b1,
                                                const float* __restrict__ W2, const float* __restrict__ b2,
                                                int B) {
    extern __shared__ char sm[];
    const int t = threadIdx.x;
    const int lane = t & 31, w = t >> 5;      // 8 warps
    const int g = lane >> 2, tig = lane & 3;
    const int n16 = (w & 3) * 16, mg = w >> 2;   // GEMM2 mapping

    char* AD = sm + OFF_AD;
    char* WT = sm + OFF_WT;
    float* b1s  = (float*)(sm + OFF_B1);
    float* b2s  = (float*)(sm + OFF_B2);
    float* pool = (float*)(sm + OFF_POOL);

    const uint32_t sb = smem_u32(sm);

    // per-lane ldmatrix/stmatrix address bases
    const int lr = lane & 15, lc8 = (lane >> 4) * 8;
    const uint32_t aAD = (uint32_t)(lr * 384 + lc8 * 2);   // + mt*6144 + kk*32, swz
    const int zrow = n16 + (lane & 7) + ((lane >> 4) << 3);
    const uint32_t aZT = (uint32_t)(zrow * 384 + ((lane & 8) ? 16 : 0));  // + kk*32 (GEMM2 bfr)
    const uint32_t aXP = (uint32_t)(((lane & 7) + ((lane >> 4) << 3)) * 384 + ((lane & 8) ? 16 : 0));
    const int zlr = (lane & 7) + ((lane >> 4) << 3);       // stsm row-part (per g4)

    // ---- one-time images ----
    for (int i = t; i < 176 * 96; i += 256) {            // A_dense fp16 [176 x 192]
        int r = i / 96, cp = i % 96;
        float2 v = *(const float2*)(g_Adense + r * 192 + cp * 2);
        *(__half2*)(AD + swz((uint32_t)(r * 384 + cp * 4))) = __floats2half2_rn(v.x, v.y);
    }
    for (int i = t; i < 64 * 32; i += 256) {             // W2^T fp16 [64 x 64]
        int n = i >> 5, cp = i & 31;
        *(__half2*)(WT + swz((uint32_t)(n * 128 + cp * 4))) =
            __floats2half2_rn(W2[(2 * cp) * 64 + n], W2[(2 * cp + 1) * 64 + n]);
    }
    for (int i = t; i < 1536; i += 256)                  // zero XP once (pads stay 0 forever)
        ((uint32_t*)(sm + OFF_XP))[i] = 0;
    if (t < 256) {                                       // W1 packed B-frag table [8][32]
        int j = t >> 5, l = t & 31;
        int tg = l & 3, gg = l >> 2;
        int n = j * 8 + gg;
        float v0 = (2 * tg < 3)     ? W1[(2 * tg) * 64 + n]     : 0.f;
        float v1 = (2 * tg + 1 < 3) ? W1[(2 * tg + 1) * 64 + n] : 0.f;
        ((uint32_t*)(sm + OFF_W1T))[t] = packh2(v0, v1);
    }
    if (t < 64) { b1s[t] = b1[t]; b2s[t] = b2[t]; }
    __syncthreads();

    // ---- W2 B-fragments for ALL 4 n16 groups (persistent, 64 regs) ----
    uint32_t wfr[4][16];
    #pragma unroll
    for (int g4 = 0; g4 < 4; g4++)
        #pragma unroll
        for (int kk = 0; kk < 4; kk++)
            #pragma unroll
            for (int s = 0; s < 2; s++) {
                int row = g4 * 16 + s * 8 + g;
                uint32_t base = (uint32_t)(row * 128 + (kk * 16 + tig * 2) * 2);
                wfr[g4][kk * 4 + s * 2 + 0] = *(const uint32_t*)(WT + swz(base));
                wfr[g4][kk * 4 + s * 2 + 1] = *(const uint32_t*)(WT + swz(base + 16));
            }

    const uint32_t* w1t = (const uint32_t*)(sm + OFF_W1T);

    for (int b = blockIdx.x; b < B; b += gridDim.x) {
        // 1. zero pool; update only the 498 valid XP entries
        if (t < 64) pool[t] = 0.f;
        for (int i = t; i < 498; i += 256) {
            int k = i / 3, n = i - 3 * k;
            *(__half*)(sm + OFF_XP + swz((uint32_t)(n * 384 + k * 2))) =
                __float2half_rn(high[(size_t)b * 498 + i]);
        }
        __syncthreads();

        // 2. fused conv1 + h1 + GEMM1 (warp owns mt = w, w+8); z -> ZT
        for (int mt = w; mt < 11; mt += 8) {
            // y0 = A_dense @ x
            float y0a[4] = {0.f, 0.f, 0.f, 0.f};
            #pragma unroll
            for (int kk = 0; kk < 11; kk++) {
                uint32_t a0, a1, a2, a3, x0, x1;
                ldsm4(a0, a1, a2, a3, sb + OFF_AD + swz((uint32_t)(mt * 6144 + kk * 32) + aAD));
                ldsm2(x0, x1, sb + OFF_XP + swz(aXP + (uint32_t)(kk * 32)));
                mma8(y0a, a0, a1, a2, a3, x0, x1);
            }
            // h1 = y0 @ W1 (bias+relu applied at pack time)
            uint32_t ya0 = packh2(y0a[0], y0a[1]);
            uint32_t ya1 = packh2(y0a[2], y0a[3]);
            float hacc[32];
            #pragma unroll
            for (int i = 0; i < 32; i++) hacc[i] = 0.f;
            #pragma unroll
            for (int j = 0; j < 8; j++)
                mma8(hacc + j * 4, ya0, ya1, 0u, 0u, w1t[j * 32 + lane], 0u);
            // A-fragments of h1 directly from registers
            uint32_t afr[16];
            #pragma unroll
            for (int kz = 0; kz < 4; kz++) {
                int j0 = 2 * kz, j1 = 2 * kz + 1;
                float b00 = b1s[j0 * 8 + 2 * tig], b01 = b1s[j0 * 8 + 2 * tig + 1];
                float b10 = b1s[j1 * 8 + 2 * tig], b11 = b1s[j1 * 8 + 2 * tig + 1];
                afr[kz * 4 + 0] = packh2(fmaxf(hacc[j0 * 4 + 0] + b00, 0.f), fmaxf(hacc[j0 * 4 + 1] + b01, 0.f));
                afr[kz * 4 + 1] = packh2(fmaxf(hacc[j0 * 4 + 2] + b00, 0.f), fmaxf(hacc[j0 * 4 + 3] + b01, 0.f));
                afr[kz * 4 + 2] = packh2(fmaxf(hacc[j1 * 4 + 0] + b10, 0.f), fmaxf(hacc[j1 * 4 + 1] + b11, 0.f));
                afr[kz * 4 + 3] = packh2(fmaxf(hacc[j1 * 4 + 2] + b10, 0.f), fmaxf(hacc[j1 * 4 + 3] + b11, 0.f));
            }
            // z[mt][all n] = h1[mt] @ W2 -> stmatrix.trans into ZT
            #pragma unroll
            for (int g4 = 0; g4 < 4; g4++) {
                float z0[8] = {0, 0, 0, 0, 0, 0, 0, 0};
                #pragma unroll
                for (int kz = 0; kz < 4; kz++) {
                    mma8(z0,     afr[kz * 4], afr[kz * 4 + 1], afr[kz * 4 + 2], afr[kz * 4 + 3],
                         wfr[g4][kz * 4 + 0], wfr[g4][kz * 4 + 1]);
                    mma8(z0 + 4, afr[kz * 4], afr[kz * 4 + 1], afr[kz * 4 + 2], afr[kz * 4 + 3],
                         wfr[g4][kz * 4 + 2], wfr[g4][kz * 4 + 3]);
                }
                uint32_t zr = (uint32_t)((g4 * 16 + zlr) * 384 + ((lane & 8) ? 16 : 0) + mt * 32);
                stsm4t(sb + OFF_ZT + swz(zr),
                       packh2(z0[0], z0[1]), packh2(z0[2], z0[3]),
                       packh2(z0[4], z0[5]), packh2(z0[6], z0[7]));
            }
        }
        __syncthreads();

        // 3. GEMM2: h2 = A_dense @ z ; fused bias+relu+pool
        uint32_t bfr[11][4];
        #pragma unroll
        for (int kk = 0; kk < 11; kk++)
            ldsm4(bfr[kk][0], bfr[kk][1], bfr[kk][2], bfr[kk][3],
                  sb + OFF_ZT + swz(aZT + (uint32_t)(kk * 32)));

        float pacc[4] = {0, 0, 0, 0};
        #pragma unroll
        for (int tt = 0; tt < 6; tt++) {
            int mt = mg + 2 * tt;
            if (mt < 11) {
                float d0[8] = {0, 0, 0, 0, 0, 0, 0, 0};
                #pragma unroll
                for (int kk = 0; kk < 11; kk++) {
                    uint32_t a0, a1, a2, a3;
                    ldsm4(a0, a1, a2, a3,
                          sb + OFF_AD + swz((uint32_t)(mt * 6144 + kk * 32) + aAD));
                    mma8(d0,     a0, a1, a2, a3, bfr[kk][0], bfr[kk][1]);
                    mma8(d0 + 4, a0, a1, a2, a3, bfr[kk][2], bfr[kk][3]);
                }
                int m0 = mt * 16 + g;
                bool v0 = (m0 < NN), v1 = (m0 + 8 < NN);
                #pragma unroll
                for (int s = 0; s < 2; s++) {
                    int c = n16 + s * 8 + tig * 2;
                    float bb0 = b2s[c], bb1 = b2s[c + 1];
                    if (v0) {
                        pacc[s * 2]     += fmaxf(d0[s * 4 + 0] + bb0, 0.f);
                        pacc[s * 2 + 1] += fmaxf(d0[s * 4 + 1] + bb1, 0.f);
                    }
                    if (v1) {
                        pacc[s * 2]     += fmaxf(d0[s * 4 + 2] + bb0, 0.f);
                        pacc[s * 2 + 1] += fmaxf(d0[s * 4 + 3] + bb1, 0.f);
                    }
                }
            }
        }
        #pragma unroll
        for (int o = 4; o <= 16; o <<= 1) {
            pacc[0] += __shfl_xor_sync(0xffffffffu, pacc[0], o);
            pacc[1] += __shfl_xor_sync(0xffffffffu, pacc[1], o);
            pacc[2] += __shfl_xor_sync(0xffffffffu, pacc[2], o);
            pacc[3] += __shfl_xor_sync(0xffffffffu, pacc[3], o);
        }
        if (g == 0) {
            atomicAdd(&pool[n16 + tig * 2],         pacc[0]);
            atomicAdd(&pool[n16 + tig * 2 + 1],     pacc[1]);
            atomicAdd(&pool[n16 + 8 + tig * 2],     pacc[2]);
            atomicAdd(&pool[n16 + 8 + tig * 2 + 1], pacc[3]);
        }
        __syncthreads();
        if (t < 64) g_gfeat[(size_t)b * NC + t] = pool[t] * (1.f / (float)NN);
        __syncthreads();
    }
}

// ---------------- head: bn2 fold (local) + fc1 + relu + classifier + log_softmax ----------------
__global__ void __launch_bounds__(256) k_head(const float* __restrict__ Wfc1, const float* __restrict__ bfc1,
                                              const float* __restrict__ glow, const float* __restrict__ blow,
                                              const float* __restrict__ Wcls, const float* __restrict__ bcls,
                                              float* __restrict__ out, int B) {
    const int t = threadIdx.x;
    const int c = t & 127;
    const int kh = t >> 7;

    __shared__ float s2[EMB], t2[EMB];
    __shared__ float comb[FCIN];
    __shared__ float partial[2 * EMB];
    __shared__ float bfcs[EMB];
    __shared__ float wcl0[EMB], wcl1[EMB];
    __shared__ float red[8];

    if (t < EMB) {
        float inv = 1.f / (float)B;
        float mu  = g_sum2[t] * inv;
        float var = g_sq2[t] * inv - mu * mu;
        float sc  = glow[t] * rsqrtf(var + BEPS);
        s2[t] = sc;
        t2[t] = blow[t] - mu * sc;
    }
    __syncthreads();

    float w[96];
    #pragma unroll
    for (int i = 0; i < 96; i++) {
        int row = kh * 96 + i;
        float v = Wfc1[row * EMB + c];
        if (row >= NC) v *= s2[row - NC];
        w[i] = v;
    }
    if (t < EMB) {
        float acc = bfc1[t];
        for (int k = 0; k < EMB; k++) acc += t2[k] * Wfc1[(NC + k) * EMB + t];
        bfcs[t] = acc;
        wcl0[t] = Wcls[t * 2];
        wcl1[t] = Wcls[t * 2 + 1];
    }

    const int spb = (B + gridDim.x - 1) / gridDim.x;
    __syncthreads();

    for (int it = 0; it < spb; it++) {
        int s = blockIdx.x * spb + it;
        bool valid = (s < B);
        if (valid) {
            if (t < NC) comb[t] = g_gfeat[(size_t)s * NC + t];
            int u = t - NC;
            if (u >= 0 && u < EMB) comb[NC + u] = g_relu_low[(size_t)s * EMB + u];
        }
        __syncthreads();
        if (valid) {
            const float* cb = comb + kh * 96;
            float a0 = 0.f, a1 = 0.f, a2 = 0.f, a3 = 0.f;
            #pragma unroll
            for (int i = 0; i < 96; i += 4) {
                a0 += w[i] * cb[i];
                a1 += w[i + 1] * cb[i + 1];
                a2 += w[i + 2] * cb[i + 2];
                a3 += w[i + 3] * cb[i + 3];
            }
            partial[kh * EMB + c] = (a0 + a1) + (a2 + a3);
        }
        __syncthreads();
        if (valid && kh == 0) {
            float h = fmaxf(partial[c] + partial[EMB + c] + bfcs[c], 0.f);
            float p0 = h * wcl0[c];
            float p1 = h * wcl1[c];
            #pragma unroll
            for (int o = 16; o > 0; o >>= 1) {
                p0 += __shfl_down_sync(0xffffffffu, p0, o);
                p1 += __shfl_down_sync(0xffffffffu, p1, o);
            }
            if ((c & 31) == 0) { red[c >> 5] = p0; red[4 + (c >> 5)] = p1; }
        }
        __syncthreads();
        if (valid && t == 0) {
            float l0 = red[0] + red[1] + red[2] + red[3] + bcls[0];
            float l1 = red[4] + red[5] + red[6] + red[7] + bcls[1];
            float m = fmaxf(l0, l1);
            float lse = m + logf(expf(l0 - m) + expf(l1 - m));
            out[(size_t)s * 2 + 0] = l0 - lse;
            out[(size_t)s * 2 + 1] = l1 - lse;
        }
        __syncthreads();
    }
}

// ---------------- launch ----------------
extern "C" void kernel_launch(void* const* d_in, const int* in_sizes, int n_in,
                              void* d_out, int out_size) {
    const float* high  = (const float*)d_in[0];
    const float* low   = (const float*)d_in[1];
    const void*  ei    = d_in[2];
    const float* g_bn  = (const float*)d_in[3];
    const float* b_bn  = (const float*)d_in[4];
    const float* W_low = (const float*)d_in[5];
    const float* bl_lw = (const float*)d_in[6];
    const float* g_lo  = (const float*)d_in[7];
    const float* b_lo  = (const float*)d_in[8];
    const float* W1    = (const float*)d_in[9];
    const float* b1    = (const float*)d_in[10];
    const float* W2    = (const float*)d_in[11];
    const float* b2    = (const float*)d_in[12];
    const float* Wfc1  = (const float*)d_in[13];
    const float* bfc1  = (const float*)d_in[14];
    const float* Wcls  = (const float*)d_in[15];
    const float* bcls  = (const float*)d_in[16];

    int B = in_sizes[0] / (NN * 3);
    int E = in_sizes[2] / 2;
    float* out = (float*)d_out;

    k_graph<<<1, 256>>>(ei, E);
    k_stats1<<<64, 256>>>(low, B);
    k_lowmlp<<<256, 128>>>(low, g_bn, b_bn, W_low, bl_lw, B);

    cudaFuncSetAttribute(k_gcn, cudaFuncAttributeMaxDynamicSharedMemorySize, GCN_SMEM);
    int grid = 296;
    if (grid > B) grid = B;
    k_gcn<<<grid, 256, GCN_SMEM>>>(high, W1, b1, W2, b2, B);

    k_head<<<296, 256>>>(Wfc1, bfc1, g_lo, b_lo, Wcls, bcls, out, B);
}